// round 1
// baseline (speedup 1.0000x reference)
#include <cuda_runtime.h>
#include <cuda_bf16.h>

// Problem constants
#define BB 2
#define SS 2048
#define EE 1024
#define HH 16
#define DD 64
#define MM (BB * SS)   // 4096

// ---------------- scratch (device globals; no allocation allowed) ----------
__device__ float g_Q[BB * HH * SS * DD];   // [b,h,s,d]
__device__ float g_K[BB * HH * SS * DD];
__device__ float g_V[BB * HH * SS * DD];
__device__ float g_ctx[BB * SS * EE];      // [b,s,e]

// ---------------- SGEMM: C = A[M,K] * W[N,K]^T + bias ----------------------
// BM=BN=128, BK=8, 256 threads, 8x8 per-thread tile.
#define BM 128
#define BN 128
#define BK 8
#define TM 8
#define TN 8

__global__ __launch_bounds__(256) void sgemm_bias_kernel(
    const float* __restrict__ A,    // [M, K] row-major
    const float* __restrict__ W,    // [N, K] row-major
    const float* __restrict__ bias, // [N]
    float* __restrict__ C,
    int M, int N, int K, int head_layout)
{
    __shared__ float As[BK][BM];
    __shared__ float Bs[BK][BN];

    const int tid = threadIdx.x;
    const int bm = blockIdx.y * BM;
    const int bn = blockIdx.x * BN;

    const int tx = tid & 15;       // 0..15 -> col groups
    const int ty = tid >> 4;       // 0..15 -> row groups

    const int ldRow = tid >> 1;        // 0..127
    const int ldCol = (tid & 1) * 4;   // 0 or 4

    const float* Aptr = A + (size_t)(bm + ldRow) * K + ldCol;
    const float* Wptr = W + (size_t)(bn + ldRow) * K + ldCol;

    float acc[TM][TN];
    #pragma unroll
    for (int i = 0; i < TM; i++)
        #pragma unroll
        for (int j = 0; j < TN; j++) acc[i][j] = 0.0f;

    for (int k0 = 0; k0 < K; k0 += BK) {
        float4 a4 = *reinterpret_cast<const float4*>(Aptr + k0);
        float4 w4 = *reinterpret_cast<const float4*>(Wptr + k0);
        As[ldCol + 0][ldRow] = a4.x;
        As[ldCol + 1][ldRow] = a4.y;
        As[ldCol + 2][ldRow] = a4.z;
        As[ldCol + 3][ldRow] = a4.w;
        Bs[ldCol + 0][ldRow] = w4.x;
        Bs[ldCol + 1][ldRow] = w4.y;
        Bs[ldCol + 2][ldRow] = w4.z;
        Bs[ldCol + 3][ldRow] = w4.w;
        __syncthreads();

        #pragma unroll
        for (int k = 0; k < BK; k++) {
            float ra[TM], rb[TN];
            float4 t0 = *reinterpret_cast<const float4*>(&As[k][ty * TM]);
            float4 t1 = *reinterpret_cast<const float4*>(&As[k][ty * TM + 4]);
            ra[0] = t0.x; ra[1] = t0.y; ra[2] = t0.z; ra[3] = t0.w;
            ra[4] = t1.x; ra[5] = t1.y; ra[6] = t1.z; ra[7] = t1.w;
            float4 u0 = *reinterpret_cast<const float4*>(&Bs[k][tx * TN]);
            float4 u1 = *reinterpret_cast<const float4*>(&Bs[k][tx * TN + 4]);
            rb[0] = u0.x; rb[1] = u0.y; rb[2] = u0.z; rb[3] = u0.w;
            rb[4] = u1.x; rb[5] = u1.y; rb[6] = u1.z; rb[7] = u1.w;
            #pragma unroll
            for (int i = 0; i < TM; i++)
                #pragma unroll
                for (int j = 0; j < TN; j++)
                    acc[i][j] += ra[i] * rb[j];
        }
        __syncthreads();
    }

    // epilogue: bias + store
    #pragma unroll
    for (int i = 0; i < TM; i++) {
        const int m = bm + ty * TM + i;
        #pragma unroll
        for (int j = 0; j < TN; j++) {
            const int n = bn + tx * TN + j;
            float v = acc[i][j] + bias[n];
            if (head_layout) {
                // m = b*S + s ; n = h*D + d -> out[((b*H+h)*S + s)*D + d]
                const int b = m >> 11;          // /2048
                const int s = m & 2047;
                const int h = n >> 6;           // /64
                const int d = n & 63;
                C[(((size_t)(b * HH + h) << 11) + s) * DD + d] = v;
            } else {
                C[(size_t)m * N + n] = v;
            }
        }
    }
}

// ---------------- Flash attention (fp32) -----------------------------------
// Block: 256 threads = 8 warps; covers 64 query rows of one (b,h).
// Each warp handles 8 query rows; keys processed in tiles of 32 (1 key/lane).
#define QTILE 64
#define KTILE 32
#define SPAD 68   // row stride in floats (16B aligned, conflict-free patterns)

__global__ __launch_bounds__(256) void flash_attn_kernel(
    const float* __restrict__ Q,  // [BH, S, D]
    const float* __restrict__ K,
    const float* __restrict__ V,
    float* __restrict__ ctx)      // [B, S, E]
{
    __shared__ float Qs[QTILE][SPAD];
    __shared__ float Ks[KTILE][SPAD];
    __shared__ float Vs[KTILE][SPAD];

    const int bh = blockIdx.y;            // 0..31
    const int q0 = blockIdx.x * QTILE;
    const int tid = threadIdx.x;
    const int warp = tid >> 5;
    const int lane = tid & 31;
    const int qrow = warp * 8;            // warp's base row inside tile

    const float* Qbh = Q + (size_t)bh * SS * DD;
    const float* Kbh = K + (size_t)bh * SS * DD;
    const float* Vbh = V + (size_t)bh * SS * DD;

    // load Q tile (64x64) -> Qs
    for (int i = tid; i < QTILE * 16; i += 256) {
        const int r = i >> 4;
        const int c = (i & 15) << 2;
        float4 v = *reinterpret_cast<const float4*>(Qbh + (size_t)(q0 + r) * DD + c);
        Qs[r][c] = v.x; Qs[r][c + 1] = v.y; Qs[r][c + 2] = v.z; Qs[r][c + 3] = v.w;
    }

    const float scale = 0.125f; // 1/sqrt(64)
    float mrun[8], lrun[8], o0[8], o1[8];
    #pragma unroll
    for (int r = 0; r < 8; r++) { mrun[r] = -1e30f; lrun[r] = 0.0f; o0[r] = 0.0f; o1[r] = 0.0f; }

    for (int k0 = 0; k0 < SS; k0 += KTILE) {
        __syncthreads();   // previous-iteration reads done (also orders Q load)
        for (int i = tid; i < KTILE * 16; i += 256) {
            const int r = i >> 4;
            const int c = (i & 15) << 2;
            float4 kv = *reinterpret_cast<const float4*>(Kbh + (size_t)(k0 + r) * DD + c);
            Ks[r][c] = kv.x; Ks[r][c + 1] = kv.y; Ks[r][c + 2] = kv.z; Ks[r][c + 3] = kv.w;
            float4 vv = *reinterpret_cast<const float4*>(Vbh + (size_t)(k0 + r) * DD + c);
            Vs[r][c] = vv.x; Vs[r][c + 1] = vv.y; Vs[r][c + 2] = vv.z; Vs[r][c + 3] = vv.w;
        }
        __syncthreads();

        // scores: lane owns key j=lane; 8 rows
        float s[8];
        #pragma unroll
        for (int r = 0; r < 8; r++) s[r] = 0.0f;
        #pragma unroll
        for (int d = 0; d < DD; d += 4) {
            float4 kd = *reinterpret_cast<const float4*>(&Ks[lane][d]);
            #pragma unroll
            for (int r = 0; r < 8; r++) {
                float4 qd = *reinterpret_cast<const float4*>(&Qs[qrow + r][d]);
                s[r] += qd.x * kd.x + qd.y * kd.y + qd.z * kd.z + qd.w * kd.w;
            }
        }

        // online softmax update
        #pragma unroll
        for (int r = 0; r < 8; r++) {
            float sr = s[r] * scale;
            float mx = sr;
            #pragma unroll
            for (int off = 16; off > 0; off >>= 1)
                mx = fmaxf(mx, __shfl_xor_sync(0xffffffffu, mx, off));
            const float mnew = fmaxf(mrun[r], mx);
            const float p = __expf(sr - mnew);
            const float corr = __expf(mrun[r] - mnew);
            float ps = p;
            #pragma unroll
            for (int off = 16; off > 0; off >>= 1)
                ps += __shfl_xor_sync(0xffffffffu, ps, off);
            lrun[r] = lrun[r] * corr + ps;
            o0[r] *= corr;
            o1[r] *= corr;
            mrun[r] = mnew;
            s[r] = p;   // reuse as probability
        }

        // PV: o[d] += sum_j p_j * V[j][d]; lane owns dims d=lane, d=lane+32
        #pragma unroll
        for (int j = 0; j < KTILE; j++) {
            const float v0 = Vs[j][lane];
            const float v1 = Vs[j][32 + lane];
            #pragma unroll
            for (int r = 0; r < 8; r++) {
                const float pj = __shfl_sync(0xffffffffu, s[r], j);
                o0[r] += pj * v0;
                o1[r] += pj * v1;
            }
        }
    }

    // write ctx[b, s, h*64 + d]
    const int b = bh >> 4;
    const int h = bh & 15;
    #pragma unroll
    for (int r = 0; r < 8; r++) {
        const int srow = q0 + qrow + r;
        const float inv = 1.0f / lrun[r];
        float* dst = ctx + ((size_t)(b * SS + srow)) * EE + h * DD;
        dst[lane] = o0[r] * inv;
        dst[32 + lane] = o1[r] * inv;
    }
}

// ---------------- launch ----------------------------------------------------
extern "C" void kernel_launch(void* const* d_in, const int* in_sizes, int n_in,
                              void* d_out, int out_size)
{
    const float* x  = (const float*)d_in[0];
    const float* Wq = (const float*)d_in[1];
    const float* bq = (const float*)d_in[2];
    const float* Wk = (const float*)d_in[3];
    const float* bk = (const float*)d_in[4];
    const float* Wv = (const float*)d_in[5];
    const float* bv = (const float*)d_in[6];
    const float* Wo = (const float*)d_in[7];
    const float* bo = (const float*)d_in[8];
    float* out = (float*)d_out;

    float *Qp, *Kp, *Vp, *Cp;
    cudaGetSymbolAddress((void**)&Qp, g_Q);
    cudaGetSymbolAddress((void**)&Kp, g_K);
    cudaGetSymbolAddress((void**)&Vp, g_V);
    cudaGetSymbolAddress((void**)&Cp, g_ctx);

    dim3 gemmGrid(EE / BN, MM / BM);   // (8, 32)
    dim3 gemmBlock(256);

    // Q/K/V projections -> [b,h,s,d]
    sgemm_bias_kernel<<<gemmGrid, gemmBlock>>>(x, Wq, bq, Qp, MM, EE, EE, 1);
    sgemm_bias_kernel<<<gemmGrid, gemmBlock>>>(x, Wk, bk, Kp, MM, EE, EE, 1);
    sgemm_bias_kernel<<<gemmGrid, gemmBlock>>>(x, Wv, bv, Vp, MM, EE, EE, 1);

    // attention -> ctx [b,s,e]
    dim3 faGrid(SS / QTILE, BB * HH);  // (32, 32)
    flash_attn_kernel<<<faGrid, dim3(256)>>>(Qp, Kp, Vp, Cp);

    // output projection -> out [b,s,e]
    sgemm_bias_kernel<<<gemmGrid, gemmBlock>>>(Cp, Wo, bo, out, MM, EE, EE, 0);
}

// round 8
// speedup vs baseline: 1.2428x; 1.2428x over previous
#include <cuda_runtime.h>
#include <cuda_bf16.h>
#include <cstdint>

// Problem constants
#define BB 2
#define SS 2048
#define EE 1024
#define HH 16
#define DD 64
#define MM (BB * SS)   // 4096

// ---------------- scratch (device globals; no allocation allowed) ----------
__device__ float g_Q[BB * HH * SS * DD];   // [b,h,s,d]
__device__ float g_K[BB * HH * SS * DD];
__device__ float g_V[BB * HH * SS * DD];
__device__ float g_ctx[BB * SS * EE];      // [b,s,e]

// ======================= helpers ===========================================
__device__ __forceinline__ uint32_t smem_u32(const void* p) {
    uint32_t a;
    asm("{ .reg .u64 t; cvta.to.shared.u64 t, %1; cvt.u32.u64 %0, t; }" : "=r"(a) : "l"(p));
    return a;
}

#define LDSM_X4(r, addr) \
    asm volatile("ldmatrix.sync.aligned.m8n8.x4.shared.b16 {%0,%1,%2,%3}, [%4];" \
        : "=r"((r)[0]), "=r"((r)[1]), "=r"((r)[2]), "=r"((r)[3]) : "r"(addr))

__device__ __forceinline__ void mma16816(float* c, const uint32_t* a,
                                         uint32_t b0, uint32_t b1) {
    asm volatile(
        "mma.sync.aligned.m16n8k16.row.col.f32.bf16.bf16.f32 "
        "{%0,%1,%2,%3}, {%4,%5,%6,%7}, {%8,%9}, {%0,%1,%2,%3};"
        : "+f"(c[0]), "+f"(c[1]), "+f"(c[2]), "+f"(c[3])
        : "r"(a[0]), "r"(a[1]), "r"(a[2]), "r"(a[3]), "r"(b0), "r"(b1));
}

__device__ __forceinline__ uint32_t pack_bf16(__nv_bfloat16 a, __nv_bfloat16 b) {
    return (uint32_t)__bfloat16_as_ushort(a) | ((uint32_t)__bfloat16_as_ushort(b) << 16);
}

// fp32x4 -> bf16 hi (uint2) + bf16 lo residual (uint2)
__device__ __forceinline__ void split_pack(float4 v, uint2& h, uint2& l) {
    __nv_bfloat16 h0 = __float2bfloat16_rn(v.x);
    __nv_bfloat16 h1 = __float2bfloat16_rn(v.y);
    __nv_bfloat16 h2 = __float2bfloat16_rn(v.z);
    __nv_bfloat16 h3 = __float2bfloat16_rn(v.w);
    __nv_bfloat16 l0 = __float2bfloat16_rn(v.x - __bfloat162float(h0));
    __nv_bfloat16 l1 = __float2bfloat16_rn(v.y - __bfloat162float(h1));
    __nv_bfloat16 l2 = __float2bfloat16_rn(v.z - __bfloat162float(h2));
    __nv_bfloat16 l3 = __float2bfloat16_rn(v.w - __bfloat162float(h3));
    h.x = pack_bf16(h0, h1); h.y = pack_bf16(h2, h3);
    l.x = pack_bf16(l0, l1); l.y = pack_bf16(l2, l3);
}

// ============ mma.sync GEMM: C = A[M,K] @ W[N,K]^T + bias ===================
// CTA tile 128x128, K-chunk 32, 256 threads (8 warps, 4x2 grid of 32x64 tiles).
// fp32 inputs split to bf16 hi/lo; 3 HMMA passes (hi*hi + hi*lo + lo*hi).
// SMEM rows padded to 80B (40 halves) -> conflict-free ldmatrix.
#define ROWH 40
#define ROWB 80
#define MAT_BYTES (128 * ROWB)        // 10240
#define STG_BYTES (4 * MAT_BYTES)     // 40960: Ahi, Alo, Bhi, Blo
#define GSMEM_TOTAL (2 * STG_BYTES)   // 81920

__global__ __launch_bounds__(256) void gemm_mma_kernel(
    const float* __restrict__ A,    // [4096, 1024] row-major
    const float* __restrict__ W,    // [1024, 1024] row-major (out-feature, K)
    const float* __restrict__ bias, // [1024]
    float* __restrict__ C,
    int head_layout)
{
    extern __shared__ __align__(16) char ds[];
    const int tid = threadIdx.x;
    const int wid = tid >> 5;
    const int lane = tid & 31;
    const int bm = blockIdx.y * 128;
    const int bn = blockIdx.x * 128;
    const int warpM = (wid & 3) * 32;
    const int warpN = (wid >> 2) * 64;

    // loader mapping: 2 threads per row, 16 consecutive k-floats per thread
    const int ldRow = tid >> 1;
    const int ldK = (tid & 1) * 16;
    const float* Ap = A + (size_t)(bm + ldRow) * 1024 + ldK;
    const float* Wp = W + (size_t)(bn + ldRow) * 1024 + ldK;

    const uint32_t sbase = smem_u32(ds);
    // per-thread store offset inside one matrix buffer
    const uint32_t stOff = (uint32_t)(ldRow * ROWB + ldK * 2);

    float acc[2][8][4];
    #pragma unroll
    for (int mt = 0; mt < 2; mt++)
        #pragma unroll
        for (int nb = 0; nb < 8; nb++)
            #pragma unroll
            for (int r = 0; r < 4; r++) acc[mt][nb][r] = 0.0f;

    float4 ra[4], rb[4];

    // ---- prologue: load + store stage 0 ----
    #pragma unroll
    for (int i = 0; i < 4; i++) {
        ra[i] = *reinterpret_cast<const float4*>(Ap + i * 4);
        rb[i] = *reinterpret_cast<const float4*>(Wp + i * 4);
    }
    {
        char* s = ds;
        uint2 h0, l0, h1, l1;
        split_pack(ra[0], h0, l0); split_pack(ra[1], h1, l1);
        *reinterpret_cast<uint4*>(s + stOff)              = make_uint4(h0.x, h0.y, h1.x, h1.y);
        *reinterpret_cast<uint4*>(s + MAT_BYTES + stOff)  = make_uint4(l0.x, l0.y, l1.x, l1.y);
        split_pack(ra[2], h0, l0); split_pack(ra[3], h1, l1);
        *reinterpret_cast<uint4*>(s + stOff + 16)             = make_uint4(h0.x, h0.y, h1.x, h1.y);
        *reinterpret_cast<uint4*>(s + MAT_BYTES + stOff + 16) = make_uint4(l0.x, l0.y, l1.x, l1.y);
        split_pack(rb[0], h0, l0); split_pack(rb[1], h1, l1);
        *reinterpret_cast<uint4*>(s + 2 * MAT_BYTES + stOff)  = make_uint4(h0.x, h0.y, h1.x, h1.y);
        *reinterpret_cast<uint4*>(s + 3 * MAT_BYTES + stOff)  = make_uint4(l0.x, l0.y, l1.x, l1.y);
        split_pack(rb[2], h0, l0); split_pack(rb[3], h1, l1);
        *reinterpret_cast<uint4*>(s + 2 * MAT_BYTES + stOff + 16) = make_uint4(h0.x, h0.y, h1.x, h1.y);
        *reinterpret_cast<uint4*>(s + 3 * MAT_BYTES + stOff + 16) = make_uint4(l0.x, l0.y, l1.x, l1.y);
    }
    __syncthreads();

    // ldmatrix address components (lane-dependent, buffer-relative)
    const int lr = lane & 7;
    const int aRow = warpM + lr + ((lane >> 3) & 1) * 8;  // + mt*16
    const int aKb  = ((lane >> 4) & 1) * 16;              // + kt*32
    const int bRow = warpN + lr + ((lane >> 4) & 1) * 8;  // + nb2*16
    const int bKb  = ((lane >> 3) & 1) * 16;              // + kt*32

    for (int s = 0; s < 32; s++) {
        const int buf = s & 1;

        if (s < 31) {
            const int kn = (s + 1) * 32;
            #pragma unroll
            for (int i = 0; i < 4; i++) {
                ra[i] = *reinterpret_cast<const float4*>(Ap + kn + i * 4);
                rb[i] = *reinterpret_cast<const float4*>(Wp + kn + i * 4);
            }
        }

        // ---- compute stage s from buf ----
        const uint32_t sA = sbase + buf * STG_BYTES;
        const uint32_t sB = sA + 2 * MAT_BYTES;
        #pragma unroll
        for (int kt = 0; kt < 2; kt++) {
            uint32_t afh[2][4], afl[2][4];
            #pragma unroll
            for (int mt = 0; mt < 2; mt++) {
                const uint32_t aaddr = sA + (uint32_t)((aRow + mt * 16) * ROWB + kt * 32 + aKb);
                LDSM_X4(afh[mt], aaddr);
                LDSM_X4(afl[mt], aaddr + MAT_BYTES);
            }
            uint32_t bfh[4][4], bfl[4][4];
            #pragma unroll
            for (int nb2 = 0; nb2 < 4; nb2++) {
                const uint32_t baddr = sB + (uint32_t)((bRow + nb2 * 16) * ROWB + kt * 32 + bKb);
                LDSM_X4(bfh[nb2], baddr);
                LDSM_X4(bfl[nb2], baddr + MAT_BYTES);
            }
            #pragma unroll
            for (int mt = 0; mt < 2; mt++) {
                #pragma unroll
                for (int nb2 = 0; nb2 < 4; nb2++) {
                    // hi * hi
                    mma16816(acc[mt][2 * nb2 + 0], afh[mt], bfh[nb2][0], bfh[nb2][1]);
                    mma16816(acc[mt][2 * nb2 + 1], afh[mt], bfh[nb2][2], bfh[nb2][3]);
                    // hi * lo
                    mma16816(acc[mt][2 * nb2 + 0], afh[mt], bfl[nb2][0], bfl[nb2][1]);
                    mma16816(acc[mt][2 * nb2 + 1], afh[mt], bfl[nb2][2], bfl[nb2][3]);
                    // lo * hi
                    mma16816(acc[mt][2 * nb2 + 0], afl[mt], bfh[nb2][0], bfh[nb2][1]);
                    mma16816(acc[mt][2 * nb2 + 1], afl[mt], bfh[nb2][2], bfh[nb2][3]);
                }
            }
        }

        if (s < 31) {
            __syncthreads();
            char* sw = ds + ((s + 1) & 1) * STG_BYTES;
            uint2 h0, l0, h1, l1;
            split_pack(ra[0], h0, l0); split_pack(ra[1], h1, l1);
            *reinterpret_cast<uint4*>(sw + stOff)              = make_uint4(h0.x, h0.y, h1.x, h1.y);
            *reinterpret_cast<uint4*>(sw + MAT_BYTES + stOff)  = make_uint4(l0.x, l0.y, l1.x, l1.y);
            split_pack(ra[2], h0, l0); split_pack(ra[3], h1, l1);
            *reinterpret_cast<uint4*>(sw + stOff + 16)             = make_uint4(h0.x, h0.y, h1.x, h1.y);
            *reinterpret_cast<uint4*>(sw + MAT_BYTES + stOff + 16) = make_uint4(l0.x, l0.y, l1.x, l1.y);
            split_pack(rb[0], h0, l0); split_pack(rb[1], h1, l1);
            *reinterpret_cast<uint4*>(sw + 2 * MAT_BYTES + stOff)  = make_uint4(h0.x, h0.y, h1.x, h1.y);
            *reinterpret_cast<uint4*>(sw + 3 * MAT_BYTES + stOff)  = make_uint4(l0.x, l0.y, l1.x, l1.y);
            split_pack(rb[2], h0, l0); split_pack(rb[3], h1, l1);
            *reinterpret_cast<uint4*>(sw + 2 * MAT_BYTES + stOff + 16) = make_uint4(h0.x, h0.y, h1.x, h1.y);
            *reinterpret_cast<uint4*>(sw + 3 * MAT_BYTES + stOff + 16) = make_uint4(l0.x, l0.y, l1.x, l1.y);
            __syncthreads();
        }
    }

    // ---- epilogue: bias + store ----
    const int gRow = lane >> 2;
    const int gCol = (lane & 3) * 2;
    #pragma unroll
    for (int mt = 0; mt < 2; mt++) {
        #pragma unroll
        for (int half = 0; half < 2; half++) {
            const int m = bm + warpM + mt * 16 + gRow + half * 8;
            const int b = m >> 11;
            const int srow = m & 2047;
            #pragma unroll
            for (int nb = 0; nb < 8; nb++) {
                const int n = bn + warpN + nb * 8 + gCol;
                float2 v;
                v.x = acc[mt][nb][half * 2 + 0] + bias[n];
                v.y = acc[mt][nb][half * 2 + 1] + bias[n + 1];
                if (head_layout) {
                    const int h = n >> 6;
                    const int d = n & 63;
                    *reinterpret_cast<float2*>(
                        C + (((size_t)(b * HH + h) << 11) + srow) * DD + d) = v;
                } else {
                    *reinterpret_cast<float2*>(C + (size_t)m * EE + n) = v;
                }
            }
        }
    }
}

// ---------------- Flash attention (fp32, unchanged) -------------------------
#define QTILE 64
#define KTILE 32
#define SPAD 68

__global__ __launch_bounds__(256) void flash_attn_kernel(
    const float* __restrict__ Q,
    const float* __restrict__ K,
    const float* __restrict__ V,
    float* __restrict__ ctx)
{
    __shared__ float Qs[QTILE][SPAD];
    __shared__ float Ks[KTILE][SPAD];
    __shared__ float Vs[KTILE][SPAD];

    const int bh = blockIdx.y;
    const int q0 = blockIdx.x * QTILE;
    const int tid = threadIdx.x;
    const int warp = tid >> 5;
    const int lane = tid & 31;
    const int qrow = warp * 8;

    const float* Qbh = Q + (size_t)bh * SS * DD;
    const float* Kbh = K + (size_t)bh * SS * DD;
    const float* Vbh = V + (size_t)bh * SS * DD;

    for (int i = tid; i < QTILE * 16; i += 256) {
        const int r = i >> 4;
        const int c = (i & 15) << 2;
        float4 v = *reinterpret_cast<const float4*>(Qbh + (size_t)(q0 + r) * DD + c);
        Qs[r][c] = v.x; Qs[r][c + 1] = v.y; Qs[r][c + 2] = v.z; Qs[r][c + 3] = v.w;
    }

    const float scale = 0.125f;
    float mrun[8], lrun[8], o0[8], o1[8];
    #pragma unroll
    for (int r = 0; r < 8; r++) { mrun[r] = -1e30f; lrun[r] = 0.0f; o0[r] = 0.0f; o1[r] = 0.0f; }

    for (int k0 = 0; k0 < SS; k0 += KTILE) {
        __syncthreads();
        for (int i = tid; i < KTILE * 16; i += 256) {
            const int r = i >> 4;
            const int c = (i & 15) << 2;
            float4 kv = *reinterpret_cast<const float4*>(Kbh + (size_t)(k0 + r) * DD + c);
            Ks[r][c] = kv.x; Ks[r][c + 1] = kv.y; Ks[r][c + 2] = kv.z; Ks[r][c + 3] = kv.w;
            float4 vv = *reinterpret_cast<const float4*>(Vbh + (size_t)(k0 + r) * DD + c);
            Vs[r][c] = vv.x; Vs[r][c + 1] = vv.y; Vs[r][c + 2] = vv.z; Vs[r][c + 3] = vv.w;
        }
        __syncthreads();

        float s[8];
        #pragma unroll
        for (int r = 0; r < 8; r++) s[r] = 0.0f;
        #pragma unroll
        for (int d = 0; d < DD; d += 4) {
            float4 kd = *reinterpret_cast<const float4*>(&Ks[lane][d]);
            #pragma unroll
            for (int r = 0; r < 8; r++) {
                float4 qd = *reinterpret_cast<const float4*>(&Qs[qrow + r][d]);
                s[r] += qd.x * kd.x + qd.y * kd.y + qd.z * kd.z + qd.w * kd.w;
            }
        }

        #pragma unroll
        for (int r = 0; r < 8; r++) {
            float sr = s[r] * scale;
            float mx = sr;
            #pragma unroll
            for (int off = 16; off > 0; off >>= 1)
                mx = fmaxf(mx, __shfl_xor_sync(0xffffffffu, mx, off));
            const float mnew = fmaxf(mrun[r], mx);
            const float p = __expf(sr - mnew);
            const float corr = __expf(mrun[r] - mnew);
            float ps = p;
            #pragma unroll
            for (int off = 16; off > 0; off >>= 1)
                ps += __shfl_xor_sync(0xffffffffu, ps, off);
            lrun[r] = lrun[r] * corr + ps;
            o0[r] *= corr;
            o1[r] *= corr;
            mrun[r] = mnew;
            s[r] = p;
        }

        #pragma unroll
        for (int j = 0; j < KTILE; j++) {
            const float v0 = Vs[j][lane];
            const float v1 = Vs[j][32 + lane];
            #pragma unroll
            for (int r = 0; r < 8; r++) {
                const float pj = __shfl_sync(0xffffffffu, s[r], j);
                o0[r] += pj * v0;
                o1[r] += pj * v1;
            }
        }
    }

    const int b = bh >> 4;
    const int h = bh & 15;
    #pragma unroll
    for (int r = 0; r < 8; r++) {
        const int srow = q0 + qrow + r;
        const float inv = 1.0f / lrun[r];
        float* dst = ctx + ((size_t)(b * SS + srow)) * EE + h * DD;
        dst[lane] = o0[r] * inv;
        dst[32 + lane] = o1[r] * inv;
    }
}

// ---------------- launch ----------------------------------------------------
extern "C" void kernel_launch(void* const* d_in, const int* in_sizes, int n_in,
                              void* d_out, int out_size)
{
    const float* x  = (const float*)d_in[0];
    const float* Wq = (const float*)d_in[1];
    const float* bq = (const float*)d_in[2];
    const float* Wk = (const float*)d_in[3];
    const float* bk = (const float*)d_in[4];
    const float* Wv = (const float*)d_in[5];
    const float* bv = (const float*)d_in[6];
    const float* Wo = (const float*)d_in[7];
    const float* bo = (const float*)d_in[8];
    float* out = (float*)d_out;

    float *Qp, *Kp, *Vp, *Cp;
    cudaGetSymbolAddress((void**)&Qp, g_Q);
    cudaGetSymbolAddress((void**)&Kp, g_K);
    cudaGetSymbolAddress((void**)&Vp, g_V);
    cudaGetSymbolAddress((void**)&Cp, g_ctx);

    cudaFuncSetAttribute(gemm_mma_kernel,
                         cudaFuncAttributeMaxDynamicSharedMemorySize, GSMEM_TOTAL);

    dim3 gemmGrid(EE / 128, MM / 128);   // (8, 32)

    gemm_mma_kernel<<<gemmGrid, 256, GSMEM_TOTAL>>>(x, Wq, bq, Qp, 1);
    gemm_mma_kernel<<<gemmGrid, 256, GSMEM_TOTAL>>>(x, Wk, bk, Kp, 1);
    gemm_mma_kernel<<<gemmGrid, 256, GSMEM_TOTAL>>>(x, Wv, bv, Vp, 1);

    dim3 faGrid(SS / QTILE, BB * HH);
    flash_attn_kernel<<<faGrid, dim3(256)>>>(Qp, Kp, Vp, Cp);

    gemm_mma_kernel<<<gemmGrid, 256, GSMEM_TOTAL>>>(Cp, Wo, bo, out, 0);
}

// round 10
// speedup vs baseline: 3.8121x; 3.0672x over previous
#include <cuda_runtime.h>
#include <cuda_bf16.h>
#include <cuda_fp16.h>
#include <cstdint>

// Problem constants
#define BB 2
#define SS 2048
#define EE 1024
#define HH 16
#define DD 64
#define MM (BB * SS)   // 4096

// ---------------- scratch (device globals; no allocation allowed) ----------
__device__ __half g_Qh[BB * HH * SS * DD];   // [b,h,s,d] fp16 (pre-scaled)
__device__ __half g_Kh[BB * HH * SS * DD];
__device__ __half g_Vh[BB * HH * SS * DD];
__device__ float  g_ctx[BB * SS * EE];       // [b,s,e]

// ======================= helpers ===========================================
__device__ __forceinline__ uint32_t smem_u32(const void* p) {
    uint32_t a;
    asm("{ .reg .u64 t; cvta.to.shared.u64 t, %1; cvt.u32.u64 %0, t; }" : "=r"(a) : "l"(p));
    return a;
}

#define LDSM_X4(r, addr) \
    asm volatile("ldmatrix.sync.aligned.m8n8.x4.shared.b16 {%0,%1,%2,%3}, [%4];" \
        : "=r"((r)[0]), "=r"((r)[1]), "=r"((r)[2]), "=r"((r)[3]) : "r"(addr))

#define LDSM_T_X4(r, addr) \
    asm volatile("ldmatrix.sync.aligned.m8n8.x4.trans.shared.b16 {%0,%1,%2,%3}, [%4];" \
        : "=r"((r)[0]), "=r"((r)[1]), "=r"((r)[2]), "=r"((r)[3]) : "r"(addr))

__device__ __forceinline__ void mma16816(float* c, const uint32_t* a,
                                         uint32_t b0, uint32_t b1) {
    asm volatile(
        "mma.sync.aligned.m16n8k16.row.col.f32.bf16.bf16.f32 "
        "{%0,%1,%2,%3}, {%4,%5,%6,%7}, {%8,%9}, {%0,%1,%2,%3};"
        : "+f"(c[0]), "+f"(c[1]), "+f"(c[2]), "+f"(c[3])
        : "r"(a[0]), "r"(a[1]), "r"(a[2]), "r"(a[3]), "r"(b0), "r"(b1));
}

__device__ __forceinline__ void mma16816h(float* c, const uint32_t* a,
                                          uint32_t b0, uint32_t b1) {
    asm volatile(
        "mma.sync.aligned.m16n8k16.row.col.f32.f16.f16.f32 "
        "{%0,%1,%2,%3}, {%4,%5,%6,%7}, {%8,%9}, {%0,%1,%2,%3};"
        : "+f"(c[0]), "+f"(c[1]), "+f"(c[2]), "+f"(c[3])
        : "r"(a[0]), "r"(a[1]), "r"(a[2]), "r"(a[3]), "r"(b0), "r"(b1));
}

__device__ __forceinline__ uint32_t pack_bf16(__nv_bfloat16 a, __nv_bfloat16 b) {
    return (uint32_t)__bfloat16_as_ushort(a) | ((uint32_t)__bfloat16_as_ushort(b) << 16);
}

// fp32x4 -> bf16 hi (uint2) + bf16 lo residual (uint2)
__device__ __forceinline__ void split_pack(float4 v, uint2& h, uint2& l) {
    __nv_bfloat16 h0 = __float2bfloat16_rn(v.x);
    __nv_bfloat16 h1 = __float2bfloat16_rn(v.y);
    __nv_bfloat16 h2 = __float2bfloat16_rn(v.z);
    __nv_bfloat16 h3 = __float2bfloat16_rn(v.w);
    __nv_bfloat16 l0 = __float2bfloat16_rn(v.x - __bfloat162float(h0));
    __nv_bfloat16 l1 = __float2bfloat16_rn(v.y - __bfloat162float(h1));
    __nv_bfloat16 l2 = __float2bfloat16_rn(v.z - __bfloat162float(h2));
    __nv_bfloat16 l3 = __float2bfloat16_rn(v.w - __bfloat162float(h3));
    h.x = pack_bf16(h0, h1); h.y = pack_bf16(h2, h3);
    l.x = pack_bf16(l0, l1); l.y = pack_bf16(l2, l3);
}

// ============ mma.sync GEMM: C = A[M,K] @ W[N,K]^T + bias ===================
// CTA tile 128x128, K-chunk 32, 256 threads (8 warps, 4x2 grid of 32x64 tiles).
// fp32 inputs split to bf16 hi/lo; 3 HMMA passes (hi*hi + hi*lo + lo*hi).
// out_mode 0: float to Cf[M,E]; out_mode 1: half2*oscale to Ch [b,h,s,d].
#define ROWB 80
#define MAT_BYTES (128 * ROWB)        // 10240
#define STG_BYTES (4 * MAT_BYTES)     // 40960: Ahi, Alo, Bhi, Blo
#define GSMEM_TOTAL (2 * STG_BYTES)   // 81920

__global__ __launch_bounds__(256) void gemm_mma_kernel(
    const float* __restrict__ A,    // [4096, 1024] row-major
    const float* __restrict__ W,    // [1024, 1024] row-major (out-feature, K)
    const float* __restrict__ bias, // [1024]
    float* __restrict__ Cf,
    __half* __restrict__ Ch,
    int out_mode, float oscale)
{
    extern __shared__ __align__(16) char ds[];
    const int tid = threadIdx.x;
    const int wid = tid >> 5;
    const int lane = tid & 31;
    const int bm = blockIdx.y * 128;
    const int bn = blockIdx.x * 128;
    const int warpM = (wid & 3) * 32;
    const int warpN = (wid >> 2) * 64;

    const int ldRow = tid >> 1;
    const int ldK = (tid & 1) * 16;
    const float* Ap = A + (size_t)(bm + ldRow) * 1024 + ldK;
    const float* Wp = W + (size_t)(bn + ldRow) * 1024 + ldK;

    const uint32_t sbase = smem_u32(ds);
    const uint32_t stOff = (uint32_t)(ldRow * ROWB + ldK * 2);

    float acc[2][8][4];
    #pragma unroll
    for (int mt = 0; mt < 2; mt++)
        #pragma unroll
        for (int nb = 0; nb < 8; nb++)
            #pragma unroll
            for (int r = 0; r < 4; r++) acc[mt][nb][r] = 0.0f;

    float4 ra[4], rb[4];

    #pragma unroll
    for (int i = 0; i < 4; i++) {
        ra[i] = *reinterpret_cast<const float4*>(Ap + i * 4);
        rb[i] = *reinterpret_cast<const float4*>(Wp + i * 4);
    }
    {
        char* s = ds;
        uint2 h0, l0, h1, l1;
        split_pack(ra[0], h0, l0); split_pack(ra[1], h1, l1);
        *reinterpret_cast<uint4*>(s + stOff)              = make_uint4(h0.x, h0.y, h1.x, h1.y);
        *reinterpret_cast<uint4*>(s + MAT_BYTES + stOff)  = make_uint4(l0.x, l0.y, l1.x, l1.y);
        split_pack(ra[2], h0, l0); split_pack(ra[3], h1, l1);
        *reinterpret_cast<uint4*>(s + stOff + 16)             = make_uint4(h0.x, h0.y, h1.x, h1.y);
        *reinterpret_cast<uint4*>(s + MAT_BYTES + stOff + 16) = make_uint4(l0.x, l0.y, l1.x, l1.y);
        split_pack(rb[0], h0, l0); split_pack(rb[1], h1, l1);
        *reinterpret_cast<uint4*>(s + 2 * MAT_BYTES + stOff)  = make_uint4(h0.x, h0.y, h1.x, h1.y);
        *reinterpret_cast<uint4*>(s + 3 * MAT_BYTES + stOff)  = make_uint4(l0.x, l0.y, l1.x, l1.y);
        split_pack(rb[2], h0, l0); split_pack(rb[3], h1, l1);
        *reinterpret_cast<uint4*>(s + 2 * MAT_BYTES + stOff + 16) = make_uint4(h0.x, h0.y, h1.x, h1.y);
        *reinterpret_cast<uint4*>(s + 3 * MAT_BYTES + stOff + 16) = make_uint4(l0.x, l0.y, l1.x, l1.y);
    }
    __syncthreads();

    const int lr = lane & 7;
    const int aRow = warpM + lr + ((lane >> 3) & 1) * 8;
    const int aKb  = ((lane >> 4) & 1) * 16;
    const int bRow = warpN + lr + ((lane >> 4) & 1) * 8;
    const int bKb  = ((lane >> 3) & 1) * 16;

    for (int s = 0; s < 32; s++) {
        const int buf = s & 1;

        if (s < 31) {
            const int kn = (s + 1) * 32;
            #pragma unroll
            for (int i = 0; i < 4; i++) {
                ra[i] = *reinterpret_cast<const float4*>(Ap + kn + i * 4);
                rb[i] = *reinterpret_cast<const float4*>(Wp + kn + i * 4);
            }
        }

        const uint32_t sA = sbase + buf * STG_BYTES;
        const uint32_t sB = sA + 2 * MAT_BYTES;
        #pragma unroll
        for (int kt = 0; kt < 2; kt++) {
            uint32_t afh[2][4], afl[2][4];
            #pragma unroll
            for (int mt = 0; mt < 2; mt++) {
                const uint32_t aaddr = sA + (uint32_t)((aRow + mt * 16) * ROWB + kt * 32 + aKb);
                LDSM_X4(afh[mt], aaddr);
                LDSM_X4(afl[mt], aaddr + MAT_BYTES);
            }
            uint32_t bfh[4][4], bfl[4][4];
            #pragma unroll
            for (int nb2 = 0; nb2 < 4; nb2++) {
                const uint32_t baddr = sB + (uint32_t)((bRow + nb2 * 16) * ROWB + kt * 32 + bKb);
                LDSM_X4(bfh[nb2], baddr);
                LDSM_X4(bfl[nb2], baddr + MAT_BYTES);
            }
            #pragma unroll
            for (int mt = 0; mt < 2; mt++) {
                #pragma unroll
                for (int nb2 = 0; nb2 < 4; nb2++) {
                    mma16816(acc[mt][2 * nb2 + 0], afh[mt], bfh[nb2][0], bfh[nb2][1]);
                    mma16816(acc[mt][2 * nb2 + 1], afh[mt], bfh[nb2][2], bfh[nb2][3]);
                    mma16816(acc[mt][2 * nb2 + 0], afh[mt], bfl[nb2][0], bfl[nb2][1]);
                    mma16816(acc[mt][2 * nb2 + 1], afh[mt], bfl[nb2][2], bfl[nb2][3]);
                    mma16816(acc[mt][2 * nb2 + 0], afl[mt], bfh[nb2][0], bfh[nb2][1]);
                    mma16816(acc[mt][2 * nb2 + 1], afl[mt], bfh[nb2][2], bfh[nb2][3]);
                }
            }
        }

        if (s < 31) {
            __syncthreads();
            char* sw = ds + ((s + 1) & 1) * STG_BYTES;
            uint2 h0, l0, h1, l1;
            split_pack(ra[0], h0, l0); split_pack(ra[1], h1, l1);
            *reinterpret_cast<uint4*>(sw + stOff)              = make_uint4(h0.x, h0.y, h1.x, h1.y);
            *reinterpret_cast<uint4*>(sw + MAT_BYTES + stOff)  = make_uint4(l0.x, l0.y, l1.x, l1.y);
            split_pack(ra[2], h0, l0); split_pack(ra[3], h1, l1);
            *reinterpret_cast<uint4*>(sw + stOff + 16)             = make_uint4(h0.x, h0.y, h1.x, h1.y);
            *reinterpret_cast<uint4*>(sw + MAT_BYTES + stOff + 16) = make_uint4(l0.x, l0.y, l1.x, l1.y);
            split_pack(rb[0], h0, l0); split_pack(rb[1], h1, l1);
            *reinterpret_cast<uint4*>(sw + 2 * MAT_BYTES + stOff)  = make_uint4(h0.x, h0.y, h1.x, h1.y);
            *reinterpret_cast<uint4*>(sw + 3 * MAT_BYTES + stOff)  = make_uint4(l0.x, l0.y, l1.x, l1.y);
            split_pack(rb[2], h0, l0); split_pack(rb[3], h1, l1);
            *reinterpret_cast<uint4*>(sw + 2 * MAT_BYTES + stOff + 16) = make_uint4(h0.x, h0.y, h1.x, h1.y);
            *reinterpret_cast<uint4*>(sw + 3 * MAT_BYTES + stOff + 16) = make_uint4(l0.x, l0.y, l1.x, l1.y);
            __syncthreads();
        }
    }

    // ---- epilogue ----
    const int gRow = lane >> 2;
    const int gCol = (lane & 3) * 2;
    #pragma unroll
    for (int mt = 0; mt < 2; mt++) {
        #pragma unroll
        for (int half_ = 0; half_ < 2; half_++) {
            const int m = bm + warpM + mt * 16 + gRow + half_ * 8;
            const int b = m >> 11;
            const int srow = m & 2047;
            #pragma unroll
            for (int nb = 0; nb < 8; nb++) {
                const int n = bn + warpN + nb * 8 + gCol;
                float vx = acc[mt][nb][half_ * 2 + 0] + bias[n];
                float vy = acc[mt][nb][half_ * 2 + 1] + bias[n + 1];
                if (out_mode == 1) {
                    const int h = n >> 6;
                    const int d = n & 63;
                    __half2 hv = __floats2half2_rn(vx * oscale, vy * oscale);
                    *reinterpret_cast<__half2*>(
                        Ch + (((size_t)(b * HH + h) << 11) + srow) * DD + d) = hv;
                } else {
                    *reinterpret_cast<float2*>(Cf + (size_t)m * EE + n) =
                        make_float2(vx, vy);
                }
            }
        }
    }
}

// ============ Flash attention via mma.sync fp16 =============================
// CTA: 128 q-rows of one (b,h); 8 warps x m16. K-tiles of 64 keys.
// Q pre-scaled by 0.125*log2(e) so p = exp2(s - m) directly.
#define FROWB 144                       // 64 halves (128B) + 16B pad
#define QS_OFF 0
#define KS_OFF (128 * FROWB)            // 18432
#define VS_OFF (KS_OFF + 64 * FROWB)    // 27648
#define FSMEM  (VS_OFF + 64 * FROWB)    // 36864

__global__ __launch_bounds__(256) void flash_mma_kernel(
    const __half* __restrict__ Q,
    const __half* __restrict__ K,
    const __half* __restrict__ V,
    float* __restrict__ ctx)            // [b,s,e]
{
    __shared__ __align__(16) char sm[FSMEM];
    const int bh = blockIdx.y;
    const int q0 = blockIdx.x * 128;
    const int tid = threadIdx.x;
    const int wid = tid >> 5;
    const int lane = tid & 31;
    const int warpM = wid * 16;
    const uint32_t sb = smem_u32(sm);

    const __half* Qbh = Q + (size_t)bh * SS * DD;
    const __half* Kbh = K + (size_t)bh * SS * DD;
    const __half* Vbh = V + (size_t)bh * SS * DD;

    // load Q tile (128 x 64 halves)
    {
        const int r = tid >> 1;
        const int ch = (tid & 1) * 32;
        const uint4* src = reinterpret_cast<const uint4*>(Qbh + (size_t)(q0 + r) * DD + ch);
        char* dst = sm + QS_OFF + r * FROWB + ch * 2;
        reinterpret_cast<uint4*>(dst)[0] = src[0];
        reinterpret_cast<uint4*>(dst)[1] = src[1];
        reinterpret_cast<uint4*>(dst)[2] = src[2];
        reinterpret_cast<uint4*>(dst)[3] = src[3];
    }
    __syncthreads();

    // hoisted Q fragments: qf[ks] covers k-dims 16ks..16ks+15
    const int lr = lane & 7;
    const int aRow = warpM + lr + ((lane >> 3) & 1) * 8;
    const int aCb  = ((lane >> 4) & 1) * 16;
    uint32_t qf[4][4];
    #pragma unroll
    for (int ks = 0; ks < 4; ks++)
        LDSM_X4(qf[ks], sb + QS_OFF + (uint32_t)(aRow * FROWB + ks * 32 + aCb));

    // K/V loader: 4 threads/row, 16 halves each
    const int lrow = tid >> 2;
    const int lcb = (tid & 3) * 32;   // byte offset in row
    uint4 kr0, kr1, vr0, vr1;
    {
        const uint4* ksrc = reinterpret_cast<const uint4*>(
            reinterpret_cast<const char*>(Kbh + (size_t)lrow * DD) + lcb);
        kr0 = ksrc[0]; kr1 = ksrc[1];
        const uint4* vsrc = reinterpret_cast<const uint4*>(
            reinterpret_cast<const char*>(Vbh + (size_t)lrow * DD) + lcb);
        vr0 = vsrc[0]; vr1 = vsrc[1];
    }

    float m0 = -1e30f, m1 = -1e30f, l0 = 0.0f, l1 = 0.0f;
    float o[8][4];
    #pragma unroll
    for (int d8 = 0; d8 < 8; d8++)
        #pragma unroll
        for (int r = 0; r < 4; r++) o[d8][r] = 0.0f;

    const int bRowK = lr + ((lane >> 4) & 1) * 8;   // K b-frag row base
    const int bCbK  = ((lane >> 3) & 1) * 16;
    const int vRowB = lr + ((lane >> 3) & 1) * 8;   // V trans row base
    const int vCbB  = ((lane >> 4) & 1) * 16;

    for (int kt = 0; kt < 32; kt++) {
        if (kt) __syncthreads();
        {
            char* kd = sm + KS_OFF + lrow * FROWB + lcb;
            reinterpret_cast<uint4*>(kd)[0] = kr0;
            reinterpret_cast<uint4*>(kd)[1] = kr1;
            char* vd = sm + VS_OFF + lrow * FROWB + lcb;
            reinterpret_cast<uint4*>(vd)[0] = vr0;
            reinterpret_cast<uint4*>(vd)[1] = vr1;
        }
        __syncthreads();
        if (kt < 31) {
            const int krow = (kt + 1) * 64 + lrow;
            const uint4* ksrc = reinterpret_cast<const uint4*>(
                reinterpret_cast<const char*>(Kbh + (size_t)krow * DD) + lcb);
            kr0 = ksrc[0]; kr1 = ksrc[1];
            const uint4* vsrc = reinterpret_cast<const uint4*>(
                reinterpret_cast<const char*>(Vbh + (size_t)krow * DD) + lcb);
            vr0 = vsrc[0]; vr1 = vsrc[1];
        }

        // ---- QK^T: 16 rows x 64 keys ----
        float sc[8][4];
        #pragma unroll
        for (int nb = 0; nb < 8; nb++)
            #pragma unroll
            for (int r = 0; r < 4; r++) sc[nb][r] = 0.0f;
        #pragma unroll
        for (int ks = 0; ks < 4; ks++) {
            #pragma unroll
            for (int ng2 = 0; ng2 < 4; ng2++) {
                uint32_t kf[4];
                LDSM_X4(kf, sb + KS_OFF +
                        (uint32_t)((ng2 * 16 + bRowK) * FROWB + ks * 32 + bCbK));
                mma16816h(sc[2 * ng2 + 0], qf[ks], kf[0], kf[1]);
                mma16816h(sc[2 * ng2 + 1], qf[ks], kf[2], kf[3]);
            }
        }

        // ---- online softmax (scores already * 0.125*log2e) ----
        float mx0 = sc[0][0], mx1 = sc[0][2];
        #pragma unroll
        for (int nb = 0; nb < 8; nb++) {
            mx0 = fmaxf(mx0, fmaxf(sc[nb][0], sc[nb][1]));
            mx1 = fmaxf(mx1, fmaxf(sc[nb][2], sc[nb][3]));
        }
        mx0 = fmaxf(mx0, __shfl_xor_sync(0xffffffffu, mx0, 1));
        mx0 = fmaxf(mx0, __shfl_xor_sync(0xffffffffu, mx0, 2));
        mx1 = fmaxf(mx1, __shfl_xor_sync(0xffffffffu, mx1, 1));
        mx1 = fmaxf(mx1, __shfl_xor_sync(0xffffffffu, mx1, 2));
        const float mn0 = fmaxf(m0, mx0);
        const float mn1 = fmaxf(m1, mx1);
        const float c0 = exp2f(m0 - mn0);
        const float c1 = exp2f(m1 - mn1);
        m0 = mn0; m1 = mn1;

        float s0 = 0.0f, s1 = 0.0f;
        uint32_t pa0[8], pa1[8];
        #pragma unroll
        for (int nb = 0; nb < 8; nb++) {
            float p00 = exp2f(sc[nb][0] - mn0);
            float p01 = exp2f(sc[nb][1] - mn0);
            float p10 = exp2f(sc[nb][2] - mn1);
            float p11 = exp2f(sc[nb][3] - mn1);
            s0 += p00 + p01;
            s1 += p10 + p11;
            __half2 h0 = __floats2half2_rn(p00, p01);
            __half2 h1 = __floats2half2_rn(p10, p11);
            pa0[nb] = *reinterpret_cast<uint32_t*>(&h0);
            pa1[nb] = *reinterpret_cast<uint32_t*>(&h1);
        }
        l0 = l0 * c0 + s0;
        l1 = l1 * c1 + s1;
        #pragma unroll
        for (int d8 = 0; d8 < 8; d8++) {
            o[d8][0] *= c0; o[d8][1] *= c0;
            o[d8][2] *= c1; o[d8][3] *= c1;
        }

        // ---- P @ V ----
        #pragma unroll
        for (int ks = 0; ks < 4; ks++) {
            uint32_t pf[4] = {pa0[2 * ks], pa1[2 * ks], pa0[2 * ks + 1], pa1[2 * ks + 1]};
            #pragma unroll
            for (int dg2 = 0; dg2 < 4; dg2++) {
                uint32_t vf[4];
                LDSM_T_X4(vf, sb + VS_OFF +
                          (uint32_t)((ks * 16 + vRowB) * FROWB + dg2 * 32 + vCbB));
                mma16816h(o[2 * dg2 + 0], pf, vf[0], vf[1]);
                mma16816h(o[2 * dg2 + 1], pf, vf[2], vf[3]);
            }
        }
    }

    // ---- finalize: reduce l across quad, normalize, store ----
    l0 += __shfl_xor_sync(0xffffffffu, l0, 1);
    l0 += __shfl_xor_sync(0xffffffffu, l0, 2);
    l1 += __shfl_xor_sync(0xffffffffu, l1, 1);
    l1 += __shfl_xor_sync(0xffffffffu, l1, 2);
    const float i0 = 1.0f / l0;
    const float i1 = 1.0f / l1;

    const int b = bh >> 4;
    const int h = bh & 15;
    const int g = lane >> 2;
    const int t2 = (lane & 3) * 2;
    const int r0 = q0 + warpM + g;
    float* d0 = ctx + ((size_t)(b * SS + r0)) * EE + h * DD;
    float* d1 = ctx + ((size_t)(b * SS + r0 + 8)) * EE + h * DD;
    #pragma unroll
    for (int d8 = 0; d8 < 8; d8++) {
        *reinterpret_cast<float2*>(d0 + d8 * 8 + t2) =
            make_float2(o[d8][0] * i0, o[d8][1] * i0);
        *reinterpret_cast<float2*>(d1 + d8 * 8 + t2) =
            make_float2(o[d8][2] * i1, o[d8][3] * i1);
    }
}

// ---------------- launch ----------------------------------------------------
extern "C" void kernel_launch(void* const* d_in, const int* in_sizes, int n_in,
                              void* d_out, int out_size)
{
    const float* x  = (const float*)d_in[0];
    const float* Wq = (const float*)d_in[1];
    const float* bq = (const float*)d_in[2];
    const float* Wk = (const float*)d_in[3];
    const float* bk = (const float*)d_in[4];
    const float* Wv = (const float*)d_in[5];
    const float* bv = (const float*)d_in[6];
    const float* Wo = (const float*)d_in[7];
    const float* bo = (const float*)d_in[8];
    float* out = (float*)d_out;

    __half *Qp, *Kp, *Vp;
    float *Cp;
    cudaGetSymbolAddress((void**)&Qp, g_Qh);
    cudaGetSymbolAddress((void**)&Kp, g_Kh);
    cudaGetSymbolAddress((void**)&Vp, g_Vh);
    cudaGetSymbolAddress((void**)&Cp, g_ctx);

    cudaFuncSetAttribute(gemm_mma_kernel,
                         cudaFuncAttributeMaxDynamicSharedMemorySize, GSMEM_TOTAL);

    dim3 gemmGrid(EE / 128, MM / 128);   // (8, 32)

    // Q pre-scaled by 0.125 * log2(e) so softmax uses exp2 directly
    const float qscale = 0.18033688011112042f;
    gemm_mma_kernel<<<gemmGrid, 256, GSMEM_TOTAL>>>(x, Wq, bq, nullptr, Qp, 1, qscale);
    gemm_mma_kernel<<<gemmGrid, 256, GSMEM_TOTAL>>>(x, Wk, bk, nullptr, Kp, 1, 1.0f);
    gemm_mma_kernel<<<gemmGrid, 256, GSMEM_TOTAL>>>(x, Wv, bv, nullptr, Vp, 1, 1.0f);

    dim3 faGrid(SS / 128, BB * HH);      // (16, 32)
    flash_mma_kernel<<<faGrid, dim3(256)>>>(Qp, Kp, Vp, Cp);

    gemm_mma_kernel<<<gemmGrid, 256, GSMEM_TOTAL>>>(Cp, Wo, bo, out, nullptr, 0, 1.0f);
}

// round 11
// speedup vs baseline: 5.5531x; 1.4567x over previous
#include <cuda_runtime.h>
#include <cuda_bf16.h>
#include <cuda_fp16.h>
#include <cstdint>

// Problem constants
#define BB 2
#define SS 2048
#define EE 1024
#define HH 16
#define DD 64
#define MM (BB * SS)   // 4096

// ---------------- scratch (device globals; no allocation allowed) ----------
__device__ __half g_Qh[BB * HH * SS * DD];   // [b,h,s,d] fp16 (pre-scaled)
__device__ __half g_Kh[BB * HH * SS * DD];
__device__ __half g_Vh[BB * HH * SS * DD];
__device__ float  g_ctx[BB * SS * EE];       // [b,s,e]

// ======================= helpers ===========================================
__device__ __forceinline__ uint32_t smem_u32(const void* p) {
    uint32_t a;
    asm("{ .reg .u64 t; cvta.to.shared.u64 t, %1; cvt.u32.u64 %0, t; }" : "=r"(a) : "l"(p));
    return a;
}

#define LDSM_X4(r, addr) \
    asm volatile("ldmatrix.sync.aligned.m8n8.x4.shared.b16 {%0,%1,%2,%3}, [%4];" \
        : "=r"((r)[0]), "=r"((r)[1]), "=r"((r)[2]), "=r"((r)[3]) : "r"(addr))

#define LDSM_T_X4(r, addr) \
    asm volatile("ldmatrix.sync.aligned.m8n8.x4.trans.shared.b16 {%0,%1,%2,%3}, [%4];" \
        : "=r"((r)[0]), "=r"((r)[1]), "=r"((r)[2]), "=r"((r)[3]) : "r"(addr))

__device__ __forceinline__ void mma16816h(float* c, const uint32_t* a,
                                          uint32_t b0, uint32_t b1) {
    asm volatile(
        "mma.sync.aligned.m16n8k16.row.col.f32.f16.f16.f32 "
        "{%0,%1,%2,%3}, {%4,%5,%6,%7}, {%8,%9}, {%0,%1,%2,%3};"
        : "+f"(c[0]), "+f"(c[1]), "+f"(c[2]), "+f"(c[3])
        : "r"(a[0]), "r"(a[1]), "r"(a[2]), "r"(a[3]), "r"(b0), "r"(b1));
}

// fp32x4 -> fp16x4 packed as uint2
__device__ __forceinline__ uint2 cvt4_h(float4 v) {
    __half2 a = __floats2half2_rn(v.x, v.y);
    __half2 b = __floats2half2_rn(v.z, v.w);
    uint2 r;
    r.x = *reinterpret_cast<uint32_t*>(&a);
    r.y = *reinterpret_cast<uint32_t*>(&b);
    return r;
}

// ============ mma.sync fp16 GEMM: C = A[M,K] @ W[N,K]^T + bias ==============
// CTA tile 128x128, K-chunk 32, 256 threads (8 warps, 4x2 grid of 32x64 tiles).
// Single-pass fp16 (fp32 accumulate). SMEM rows padded to 80B -> conflict-free
// ldmatrix. Stage: Ah (128x80B) + Bh (128x80B); double-buffered.
#define ROWB 80
#define MAT_BYTES (128 * ROWB)        // 10240
#define STG_BYTES (2 * MAT_BYTES)     // 20480: Ah, Bh
#define GSMEM_TOTAL (2 * STG_BYTES)   // 40960

__global__ __launch_bounds__(256) void gemm_mma_kernel(
    const float* __restrict__ A,    // [4096, 1024] row-major
    const float* __restrict__ W,    // [1024, 1024] row-major (out-feature, K)
    const float* __restrict__ bias, // [1024]
    float* __restrict__ Cf,
    __half* __restrict__ Ch,
    int out_mode, float oscale)
{
    extern __shared__ __align__(16) char ds[];
    const int tid = threadIdx.x;
    const int wid = tid >> 5;
    const int lane = tid & 31;
    const int bm = blockIdx.y * 128;
    const int bn = blockIdx.x * 128;
    const int warpM = (wid & 3) * 32;
    const int warpN = (wid >> 2) * 64;

    // loader: 2 threads per row, 16 consecutive k-floats per thread
    const int ldRow = tid >> 1;
    const int ldK = (tid & 1) * 16;
    const float* Ap = A + (size_t)(bm + ldRow) * 1024 + ldK;
    const float* Wp = W + (size_t)(bn + ldRow) * 1024 + ldK;

    const uint32_t sbase = smem_u32(ds);
    const uint32_t stOff = (uint32_t)(ldRow * ROWB + ldK * 2);  // bytes

    float acc[2][8][4];
    #pragma unroll
    for (int mt = 0; mt < 2; mt++)
        #pragma unroll
        for (int nb = 0; nb < 8; nb++)
            #pragma unroll
            for (int r = 0; r < 4; r++) acc[mt][nb][r] = 0.0f;

    float4 ra[4], rb[4];

    // ---- prologue: load + convert + store stage 0 ----
    #pragma unroll
    for (int i = 0; i < 4; i++) {
        ra[i] = *reinterpret_cast<const float4*>(Ap + i * 4);
        rb[i] = *reinterpret_cast<const float4*>(Wp + i * 4);
    }
    {
        char* s = ds;
        uint2 a0 = cvt4_h(ra[0]), a1 = cvt4_h(ra[1]);
        uint2 a2 = cvt4_h(ra[2]), a3 = cvt4_h(ra[3]);
        *reinterpret_cast<uint4*>(s + stOff)      = make_uint4(a0.x, a0.y, a1.x, a1.y);
        *reinterpret_cast<uint4*>(s + stOff + 16) = make_uint4(a2.x, a2.y, a3.x, a3.y);
        uint2 b0 = cvt4_h(rb[0]), b1 = cvt4_h(rb[1]);
        uint2 b2 = cvt4_h(rb[2]), b3 = cvt4_h(rb[3]);
        *reinterpret_cast<uint4*>(s + MAT_BYTES + stOff)      = make_uint4(b0.x, b0.y, b1.x, b1.y);
        *reinterpret_cast<uint4*>(s + MAT_BYTES + stOff + 16) = make_uint4(b2.x, b2.y, b3.x, b3.y);
    }
    __syncthreads();

    // ldmatrix address components
    const int lr = lane & 7;
    const int aRow = warpM + lr + ((lane >> 3) & 1) * 8;
    const int aKb  = ((lane >> 4) & 1) * 16;
    const int bRow = warpN + lr + ((lane >> 4) & 1) * 8;
    const int bKb  = ((lane >> 3) & 1) * 16;

    for (int s = 0; s < 32; s++) {
        const int buf = s & 1;

        if (s < 31) {
            const int kn = (s + 1) * 32;
            #pragma unroll
            for (int i = 0; i < 4; i++) {
                ra[i] = *reinterpret_cast<const float4*>(Ap + kn + i * 4);
                rb[i] = *reinterpret_cast<const float4*>(Wp + kn + i * 4);
            }
        }

        // ---- compute stage s ----
        const uint32_t sA = sbase + buf * STG_BYTES;
        const uint32_t sB = sA + MAT_BYTES;
        #pragma unroll
        for (int kt = 0; kt < 2; kt++) {
            uint32_t af[2][4];
            #pragma unroll
            for (int mt = 0; mt < 2; mt++)
                LDSM_X4(af[mt], sA + (uint32_t)((aRow + mt * 16) * ROWB + kt * 32 + aKb));
            uint32_t bf[4][4];
            #pragma unroll
            for (int nb2 = 0; nb2 < 4; nb2++)
                LDSM_X4(bf[nb2], sB + (uint32_t)((bRow + nb2 * 16) * ROWB + kt * 32 + bKb));
            #pragma unroll
            for (int mt = 0; mt < 2; mt++) {
                #pragma unroll
                for (int nb2 = 0; nb2 < 4; nb2++) {
                    mma16816h(acc[mt][2 * nb2 + 0], af[mt], bf[nb2][0], bf[nb2][1]);
                    mma16816h(acc[mt][2 * nb2 + 1], af[mt], bf[nb2][2], bf[nb2][3]);
                }
            }
        }

        if (s < 31) {
            __syncthreads();
            char* sw = ds + ((s + 1) & 1) * STG_BYTES;
            uint2 a0 = cvt4_h(ra[0]), a1 = cvt4_h(ra[1]);
            uint2 a2 = cvt4_h(ra[2]), a3 = cvt4_h(ra[3]);
            *reinterpret_cast<uint4*>(sw + stOff)      = make_uint4(a0.x, a0.y, a1.x, a1.y);
            *reinterpret_cast<uint4*>(sw + stOff + 16) = make_uint4(a2.x, a2.y, a3.x, a3.y);
            uint2 b0 = cvt4_h(rb[0]), b1 = cvt4_h(rb[1]);
            uint2 b2 = cvt4_h(rb[2]), b3 = cvt4_h(rb[3]);
            *reinterpret_cast<uint4*>(sw + MAT_BYTES + stOff)      = make_uint4(b0.x, b0.y, b1.x, b1.y);
            *reinterpret_cast<uint4*>(sw + MAT_BYTES + stOff + 16) = make_uint4(b2.x, b2.y, b3.x, b3.y);
            __syncthreads();
        }
    }

    // ---- epilogue ----
    const int gRow = lane >> 2;
    const int gCol = (lane & 3) * 2;
    #pragma unroll
    for (int mt = 0; mt < 2; mt++) {
        #pragma unroll
        for (int half_ = 0; half_ < 2; half_++) {
            const int m = bm + warpM + mt * 16 + gRow + half_ * 8;
            const int b = m >> 11;
            const int srow = m & 2047;
            #pragma unroll
            for (int nb = 0; nb < 8; nb++) {
                const int n = bn + warpN + nb * 8 + gCol;
                float vx = acc[mt][nb][half_ * 2 + 0] + bias[n];
                float vy = acc[mt][nb][half_ * 2 + 1] + bias[n + 1];
                if (out_mode == 1) {
                    const int h = n >> 6;
                    const int d = n & 63;
                    __half2 hv = __floats2half2_rn(vx * oscale, vy * oscale);
                    *reinterpret_cast<__half2*>(
                        Ch + (((size_t)(b * HH + h) << 11) + srow) * DD + d) = hv;
                } else {
                    *reinterpret_cast<float2*>(Cf + (size_t)m * EE + n) =
                        make_float2(vx, vy);
                }
            }
        }
    }
}

// ============ Flash attention via mma.sync fp16 =============================
// CTA: 128 q-rows of one (b,h); 8 warps x m16. K-tiles of 64 keys.
// Q pre-scaled by 0.125*log2(e) so p = exp2(s - m) directly.
#define FROWB 144                       // 64 halves (128B) + 16B pad
#define QS_OFF 0
#define KS_OFF (128 * FROWB)            // 18432
#define VS_OFF (KS_OFF + 64 * FROWB)    // 27648
#define FSMEM  (VS_OFF + 64 * FROWB)    // 36864

__global__ __launch_bounds__(256) void flash_mma_kernel(
    const __half* __restrict__ Q,
    const __half* __restrict__ K,
    const __half* __restrict__ V,
    float* __restrict__ ctx)            // [b,s,e]
{
    __shared__ __align__(16) char sm[FSMEM];
    const int bh = blockIdx.y;
    const int q0 = blockIdx.x * 128;
    const int tid = threadIdx.x;
    const int wid = tid >> 5;
    const int lane = tid & 31;
    const int warpM = wid * 16;
    const uint32_t sb = smem_u32(sm);

    const __half* Qbh = Q + (size_t)bh * SS * DD;
    const __half* Kbh = K + (size_t)bh * SS * DD;
    const __half* Vbh = V + (size_t)bh * SS * DD;

    // load Q tile (128 x 64 halves)
    {
        const int r = tid >> 1;
        const int ch = (tid & 1) * 32;
        const uint4* src = reinterpret_cast<const uint4*>(Qbh + (size_t)(q0 + r) * DD + ch);
        char* dst = sm + QS_OFF + r * FROWB + ch * 2;
        reinterpret_cast<uint4*>(dst)[0] = src[0];
        reinterpret_cast<uint4*>(dst)[1] = src[1];
        reinterpret_cast<uint4*>(dst)[2] = src[2];
        reinterpret_cast<uint4*>(dst)[3] = src[3];
    }
    __syncthreads();

    // hoisted Q fragments
    const int lr = lane & 7;
    const int aRow = warpM + lr + ((lane >> 3) & 1) * 8;
    const int aCb  = ((lane >> 4) & 1) * 16;
    uint32_t qf[4][4];
    #pragma unroll
    for (int ks = 0; ks < 4; ks++)
        LDSM_X4(qf[ks], sb + QS_OFF + (uint32_t)(aRow * FROWB + ks * 32 + aCb));

    // K/V loader: 4 threads/row, 16 halves each
    const int lrow = tid >> 2;
    const int lcb = (tid & 3) * 32;
    uint4 kr0, kr1, vr0, vr1;
    {
        const uint4* ksrc = reinterpret_cast<const uint4*>(
            reinterpret_cast<const char*>(Kbh + (size_t)lrow * DD) + lcb);
        kr0 = ksrc[0]; kr1 = ksrc[1];
        const uint4* vsrc = reinterpret_cast<const uint4*>(
            reinterpret_cast<const char*>(Vbh + (size_t)lrow * DD) + lcb);
        vr0 = vsrc[0]; vr1 = vsrc[1];
    }

    float m0 = -1e30f, m1 = -1e30f, l0 = 0.0f, l1 = 0.0f;
    float o[8][4];
    #pragma unroll
    for (int d8 = 0; d8 < 8; d8++)
        #pragma unroll
        for (int r = 0; r < 4; r++) o[d8][r] = 0.0f;

    const int bRowK = lr + ((lane >> 4) & 1) * 8;
    const int bCbK  = ((lane >> 3) & 1) * 16;
    const int vRowB = lr + ((lane >> 3) & 1) * 8;
    const int vCbB  = ((lane >> 4) & 1) * 16;

    for (int kt = 0; kt < 32; kt++) {
        if (kt) __syncthreads();
        {
            char* kd = sm + KS_OFF + lrow * FROWB + lcb;
            reinterpret_cast<uint4*>(kd)[0] = kr0;
            reinterpret_cast<uint4*>(kd)[1] = kr1;
            char* vd = sm + VS_OFF + lrow * FROWB + lcb;
            reinterpret_cast<uint4*>(vd)[0] = vr0;
            reinterpret_cast<uint4*>(vd)[1] = vr1;
        }
        __syncthreads();
        if (kt < 31) {
            const int krow = (kt + 1) * 64 + lrow;
            const uint4* ksrc = reinterpret_cast<const uint4*>(
                reinterpret_cast<const char*>(Kbh + (size_t)krow * DD) + lcb);
            kr0 = ksrc[0]; kr1 = ksrc[1];
            const uint4* vsrc = reinterpret_cast<const uint4*>(
                reinterpret_cast<const char*>(Vbh + (size_t)krow * DD) + lcb);
            vr0 = vsrc[0]; vr1 = vsrc[1];
        }

        // ---- QK^T ----
        float sc[8][4];
        #pragma unroll
        for (int nb = 0; nb < 8; nb++)
            #pragma unroll
            for (int r = 0; r < 4; r++) sc[nb][r] = 0.0f;
        #pragma unroll
        for (int ks = 0; ks < 4; ks++) {
            #pragma unroll
            for (int ng2 = 0; ng2 < 4; ng2++) {
                uint32_t kf[4];
                LDSM_X4(kf, sb + KS_OFF +
                        (uint32_t)((ng2 * 16 + bRowK) * FROWB + ks * 32 + bCbK));
                mma16816h(sc[2 * ng2 + 0], qf[ks], kf[0], kf[1]);
                mma16816h(sc[2 * ng2 + 1], qf[ks], kf[2], kf[3]);
            }
        }

        // ---- online softmax ----
        float mx0 = sc[0][0], mx1 = sc[0][2];
        #pragma unroll
        for (int nb = 0; nb < 8; nb++) {
            mx0 = fmaxf(mx0, fmaxf(sc[nb][0], sc[nb][1]));
            mx1 = fmaxf(mx1, fmaxf(sc[nb][2], sc[nb][3]));
        }
        mx0 = fmaxf(mx0, __shfl_xor_sync(0xffffffffu, mx0, 1));
        mx0 = fmaxf(mx0, __shfl_xor_sync(0xffffffffu, mx0, 2));
        mx1 = fmaxf(mx1, __shfl_xor_sync(0xffffffffu, mx1, 1));
        mx1 = fmaxf(mx1, __shfl_xor_sync(0xffffffffu, mx1, 2));
        const float mn0 = fmaxf(m0, mx0);
        const float mn1 = fmaxf(m1, mx1);
        const float c0 = exp2f(m0 - mn0);
        const float c1 = exp2f(m1 - mn1);
        m0 = mn0; m1 = mn1;

        float s0 = 0.0f, s1 = 0.0f;
        uint32_t pa0[8], pa1[8];
        #pragma unroll
        for (int nb = 0; nb < 8; nb++) {
            float p00 = exp2f(sc[nb][0] - mn0);
            float p01 = exp2f(sc[nb][1] - mn0);
            float p10 = exp2f(sc[nb][2] - mn1);
            float p11 = exp2f(sc[nb][3] - mn1);
            s0 += p00 + p01;
            s1 += p10 + p11;
            __half2 h0 = __floats2half2_rn(p00, p01);
            __half2 h1 = __floats2half2_rn(p10, p11);
            pa0[nb] = *reinterpret_cast<uint32_t*>(&h0);
            pa1[nb] = *reinterpret_cast<uint32_t*>(&h1);
        }
        l0 = l0 * c0 + s0;
        l1 = l1 * c1 + s1;
        #pragma unroll
        for (int d8 = 0; d8 < 8; d8++) {
            o[d8][0] *= c0; o[d8][1] *= c0;
            o[d8][2] *= c1; o[d8][3] *= c1;
        }

        // ---- P @ V ----
        #pragma unroll
        for (int ks = 0; ks < 4; ks++) {
            uint32_t pf[4] = {pa0[2 * ks], pa1[2 * ks], pa0[2 * ks + 1], pa1[2 * ks + 1]};
            #pragma unroll
            for (int dg2 = 0; dg2 < 4; dg2++) {
                uint32_t vf[4];
                LDSM_T_X4(vf, sb + VS_OFF +
                          (uint32_t)((ks * 16 + vRowB) * FROWB + dg2 * 32 + vCbB));
                mma16816h(o[2 * dg2 + 0], pf, vf[0], vf[1]);
                mma16816h(o[2 * dg2 + 1], pf, vf[2], vf[3]);
            }
        }
    }

    // ---- finalize ----
    l0 += __shfl_xor_sync(0xffffffffu, l0, 1);
    l0 += __shfl_xor_sync(0xffffffffu, l0, 2);
    l1 += __shfl_xor_sync(0xffffffffu, l1, 1);
    l1 += __shfl_xor_sync(0xffffffffu, l1, 2);
    const float i0 = 1.0f / l0;
    const float i1 = 1.0f / l1;

    const int b = bh >> 4;
    const int h = bh & 15;
    const int g = lane >> 2;
    const int t2 = (lane & 3) * 2;
    const int r0 = q0 + warpM + g;
    float* d0 = ctx + ((size_t)(b * SS + r0)) * EE + h * DD;
    float* d1 = ctx + ((size_t)(b * SS + r0 + 8)) * EE + h * DD;
    #pragma unroll
    for (int d8 = 0; d8 < 8; d8++) {
        *reinterpret_cast<float2*>(d0 + d8 * 8 + t2) =
            make_float2(o[d8][0] * i0, o[d8][1] * i0);
        *reinterpret_cast<float2*>(d1 + d8 * 8 + t2) =
            make_float2(o[d8][2] * i1, o[d8][3] * i1);
    }
}

// ---------------- launch ----------------------------------------------------
extern "C" void kernel_launch(void* const* d_in, const int* in_sizes, int n_in,
                              void* d_out, int out_size)
{
    const float* x  = (const float*)d_in[0];
    const float* Wq = (const float*)d_in[1];
    const float* bq = (const float*)d_in[2];
    const float* Wk = (const float*)d_in[3];
    const float* bk = (const float*)d_in[4];
    const float* Wv = (const float*)d_in[5];
    const float* bv = (const float*)d_in[6];
    const float* Wo = (const float*)d_in[7];
    const float* bo = (const float*)d_in[8];
    float* out = (float*)d_out;

    __half *Qp, *Kp, *Vp;
    float *Cp;
    cudaGetSymbolAddress((void**)&Qp, g_Qh);
    cudaGetSymbolAddress((void**)&Kp, g_Kh);
    cudaGetSymbolAddress((void**)&Vp, g_Vh);
    cudaGetSymbolAddress((void**)&Cp, g_ctx);

    cudaFuncSetAttribute(gemm_mma_kernel,
                         cudaFuncAttributeMaxDynamicSharedMemorySize, GSMEM_TOTAL);

    dim3 gemmGrid(EE / 128, MM / 128);   // (8, 32)

    // Q pre-scaled by 0.125 * log2(e) so softmax uses exp2 directly
    const float qscale = 0.18033688011112042f;
    gemm_mma_kernel<<<gemmGrid, 256, GSMEM_TOTAL>>>(x, Wq, bq, nullptr, Qp, 1, qscale);
    gemm_mma_kernel<<<gemmGrid, 256, GSMEM_TOTAL>>>(x, Wk, bk, nullptr, Kp, 1, 1.0f);
    gemm_mma_kernel<<<gemmGrid, 256, GSMEM_TOTAL>>>(x, Wv, bv, nullptr, Vp, 1, 1.0f);

    dim3 faGrid(SS / 128, BB * HH);      // (16, 32)
    flash_mma_kernel<<<faGrid, dim3(256)>>>(Qp, Kp, Vp, Cp);

    gemm_mma_kernel<<<gemmGrid, 256, GSMEM_TOTAL>>>(Cp, Wo, bo, out, nullptr, 0, 1.0f);
}

// round 13
// speedup vs baseline: 7.0654x; 1.2723x over previous
#include <cuda_runtime.h>
#include <cuda_bf16.h>
#include <cuda_fp16.h>
#include <cstdint>

// Problem constants
#define BB 2
#define SS 2048
#define EE 1024
#define HH 16
#define DD 64
#define MM (BB * SS)   // 4096

// ---------------- scratch (device globals; no allocation allowed) ----------
__device__ __half g_xh[MM * EE];             // fp16 copy of x [4096,1024]
__device__ __half g_Wqh[EE * EE];
__device__ __half g_Wkh[EE * EE];
__device__ __half g_Wvh[EE * EE];
__device__ __half g_Woh[EE * EE];
__device__ __half g_Qh[BB * HH * SS * DD];   // [b,h,s,d] fp16 (pre-scaled)
__device__ __half g_Kh[BB * HH * SS * DD];
__device__ __half g_Vh[BB * HH * SS * DD];
__device__ __half g_ctxh[BB * SS * EE];      // [b,s,e] fp16

// ======================= helpers ===========================================
__device__ __forceinline__ uint32_t smem_u32(const void* p) {
    uint32_t a;
    asm("{ .reg .u64 t; cvta.to.shared.u64 t, %1; cvt.u32.u64 %0, t; }" : "=r"(a) : "l"(p));
    return a;
}

#define LDSM_X4(r, addr) \
    asm volatile("ldmatrix.sync.aligned.m8n8.x4.shared.b16 {%0,%1,%2,%3}, [%4];" \
        : "=r"((r)[0]), "=r"((r)[1]), "=r"((r)[2]), "=r"((r)[3]) : "r"(addr))

#define LDSM_T_X4(r, addr) \
    asm volatile("ldmatrix.sync.aligned.m8n8.x4.trans.shared.b16 {%0,%1,%2,%3}, [%4];" \
        : "=r"((r)[0]), "=r"((r)[1]), "=r"((r)[2]), "=r"((r)[3]) : "r"(addr))

__device__ __forceinline__ void mma16816h(float* c, const uint32_t* a,
                                          uint32_t b0, uint32_t b1) {
    asm volatile(
        "mma.sync.aligned.m16n8k16.row.col.f32.f16.f16.f32 "
        "{%0,%1,%2,%3}, {%4,%5,%6,%7}, {%8,%9}, {%0,%1,%2,%3};"
        : "+f"(c[0]), "+f"(c[1]), "+f"(c[2]), "+f"(c[3])
        : "r"(a[0]), "r"(a[1]), "r"(a[2]), "r"(a[3]), "r"(b0), "r"(b1));
}

// ================ fp32 -> fp16 convert pass (8 elts/thread) =================
__global__ __launch_bounds__(256) void cvt_f2h_kernel(
    const float* __restrict__ src, __half* __restrict__ dst, int n)
{
    const int i = (blockIdx.x * 256 + threadIdx.x) * 8;
    if (i >= n) return;
    float4 a = *reinterpret_cast<const float4*>(src + i);
    float4 b = *reinterpret_cast<const float4*>(src + i + 4);
    __half2 h0 = __floats2half2_rn(a.x, a.y);
    __half2 h1 = __floats2half2_rn(a.z, a.w);
    __half2 h2 = __floats2half2_rn(b.x, b.y);
    __half2 h3 = __floats2half2_rn(b.z, b.w);
    uint4 o;
    o.x = *reinterpret_cast<uint32_t*>(&h0);
    o.y = *reinterpret_cast<uint32_t*>(&h1);
    o.z = *reinterpret_cast<uint32_t*>(&h2);
    o.w = *reinterpret_cast<uint32_t*>(&h3);
    *reinterpret_cast<uint4*>(dst + i) = o;
}

// ============ mma.sync fp16 GEMM: C = A[M,K] @ W[N,K]^T + bias ==============
// All-fp16 operands in GMEM. CTA tile 128x128, K-chunk 32, 256 threads
// (8 warps, 4x2 grid of 32x64 tiles). SMEM rows 80B -> conflict-free ldmatrix.
#define ROWB 80
#define MAT_BYTES (128 * ROWB)        // 10240
#define STG_BYTES (2 * MAT_BYTES)     // 20480: Ah, Bh
#define GSMEM_TOTAL (2 * STG_BYTES)   // 40960

__global__ __launch_bounds__(256) void gemm_mma_kernel(
    const __half* __restrict__ A,   // [4096, 1024] row-major fp16
    const __half* __restrict__ W,   // [1024, 1024] row-major fp16
    const float* __restrict__ bias, // [1024]
    float* __restrict__ Cf,
    __half* __restrict__ Ch,
    int out_mode, float oscale)
{
    extern __shared__ __align__(16) char ds[];
    const int tid = threadIdx.x;
    const int wid = tid >> 5;
    const int lane = tid & 31;
    const int bm = blockIdx.y * 128;
    const int bn = blockIdx.x * 128;
    const int warpM = (wid & 3) * 32;
    const int warpN = (wid >> 2) * 64;

    // loader: 2 threads per row, 16 consecutive k-halves per thread
    const int ldRow = tid >> 1;
    const int ldH = (tid & 1) * 16;
    const __half* Ap = A + (size_t)(bm + ldRow) * 1024 + ldH;
    const __half* Wp = W + (size_t)(bn + ldRow) * 1024 + ldH;

    const uint32_t sbase = smem_u32(ds);
    const uint32_t stOff = (uint32_t)(ldRow * ROWB + ldH * 2);  // bytes

    float acc[2][8][4];
    #pragma unroll
    for (int mt = 0; mt < 2; mt++)
        #pragma unroll
        for (int nb = 0; nb < 8; nb++)
            #pragma unroll
            for (int r = 0; r < 4; r++) acc[mt][nb][r] = 0.0f;

    uint4 ra0, ra1, rb0, rb1;

    // ---- prologue: stage 0 ----
    ra0 = *reinterpret_cast<const uint4*>(Ap);
    ra1 = *reinterpret_cast<const uint4*>(Ap + 8);
    rb0 = *reinterpret_cast<const uint4*>(Wp);
    rb1 = *reinterpret_cast<const uint4*>(Wp + 8);
    {
        char* s = ds;
        *reinterpret_cast<uint4*>(s + stOff)                   = ra0;
        *reinterpret_cast<uint4*>(s + stOff + 16)              = ra1;
        *reinterpret_cast<uint4*>(s + MAT_BYTES + stOff)       = rb0;
        *reinterpret_cast<uint4*>(s + MAT_BYTES + stOff + 16)  = rb1;
    }
    __syncthreads();

    // ldmatrix address components
    const int lr = lane & 7;
    const int aRow = warpM + lr + ((lane >> 3) & 1) * 8;
    const int aKb  = ((lane >> 4) & 1) * 16;
    const int bRow = warpN + lr + ((lane >> 4) & 1) * 8;
    const int bKb  = ((lane >> 3) & 1) * 16;

    for (int s = 0; s < 32; s++) {
        const int buf = s & 1;

        if (s < 31) {
            const int kn = (s + 1) * 32;
            ra0 = *reinterpret_cast<const uint4*>(Ap + kn);
            ra1 = *reinterpret_cast<const uint4*>(Ap + kn + 8);
            rb0 = *reinterpret_cast<const uint4*>(Wp + kn);
            rb1 = *reinterpret_cast<const uint4*>(Wp + kn + 8);
        }

        // ---- compute stage s ----
        const uint32_t sA = sbase + buf * STG_BYTES;
        const uint32_t sB = sA + MAT_BYTES;
        #pragma unroll
        for (int kt = 0; kt < 2; kt++) {
            uint32_t af[2][4];
            #pragma unroll
            for (int mt = 0; mt < 2; mt++)
                LDSM_X4(af[mt], sA + (uint32_t)((aRow + mt * 16) * ROWB + kt * 32 + aKb));
            uint32_t bf[4][4];
            #pragma unroll
            for (int nb2 = 0; nb2 < 4; nb2++)
                LDSM_X4(bf[nb2], sB + (uint32_t)((bRow + nb2 * 16) * ROWB + kt * 32 + bKb));
            #pragma unroll
            for (int mt = 0; mt < 2; mt++) {
                #pragma unroll
                for (int nb2 = 0; nb2 < 4; nb2++) {
                    mma16816h(acc[mt][2 * nb2 + 0], af[mt], bf[nb2][0], bf[nb2][1]);
                    mma16816h(acc[mt][2 * nb2 + 1], af[mt], bf[nb2][2], bf[nb2][3]);
                }
            }
        }

        if (s < 31) {
            __syncthreads();
            char* sw = ds + ((s + 1) & 1) * STG_BYTES;
            *reinterpret_cast<uint4*>(sw + stOff)                  = ra0;
            *reinterpret_cast<uint4*>(sw + stOff + 16)             = ra1;
            *reinterpret_cast<uint4*>(sw + MAT_BYTES + stOff)      = rb0;
            *reinterpret_cast<uint4*>(sw + MAT_BYTES + stOff + 16) = rb1;
            __syncthreads();
        }
    }

    // ---- epilogue ----
    const int gRow = lane >> 2;
    const int gCol = (lane & 3) * 2;
    #pragma unroll
    for (int mt = 0; mt < 2; mt++) {
        #pragma unroll
        for (int half_ = 0; half_ < 2; half_++) {
            const int m = bm + warpM + mt * 16 + gRow + half_ * 8;
            const int b = m >> 11;
            const int srow = m & 2047;
            #pragma unroll
            for (int nb = 0; nb < 8; nb++) {
                const int n = bn + warpN + nb * 8 + gCol;
                float vx = acc[mt][nb][half_ * 2 + 0] + bias[n];
                float vy = acc[mt][nb][half_ * 2 + 1] + bias[n + 1];
                if (out_mode == 1) {
                    const int h = n >> 6;
                    const int d = n & 63;
                    __half2 hv = __floats2half2_rn(vx * oscale, vy * oscale);
                    *reinterpret_cast<__half2*>(
                        Ch + (((size_t)(b * HH + h) << 11) + srow) * DD + d) = hv;
                } else {
                    *reinterpret_cast<float2*>(Cf + (size_t)m * EE + n) =
                        make_float2(vx, vy);
                }
            }
        }
    }
}

// ============ Flash attention via mma.sync fp16 =============================
// CTA: 128 q-rows of one (b,h); 8 warps x m16. K-tiles of 64 keys.
// Q pre-scaled by 0.125*log2(e) so p = exp2(s - m) directly. ctx out fp16.
#define FROWB 144                       // 64 halves (128B) + 16B pad
#define QS_OFF 0
#define KS_OFF (128 * FROWB)            // 18432
#define VS_OFF (KS_OFF + 64 * FROWB)    // 27648
#define FSMEM  (VS_OFF + 64 * FROWB)    // 36864

__global__ __launch_bounds__(256) void flash_mma_kernel(
    const __half* __restrict__ Q,
    const __half* __restrict__ K,
    const __half* __restrict__ V,
    __half* __restrict__ ctx)           // [b,s,e] fp16
{
    __shared__ __align__(16) char sm[FSMEM];
    const int bh = blockIdx.y;
    const int q0 = blockIdx.x * 128;
    const int tid = threadIdx.x;
    const int wid = tid >> 5;
    const int lane = tid & 31;
    const int warpM = wid * 16;
    const uint32_t sb = smem_u32(sm);

    const __half* Qbh = Q + (size_t)bh * SS * DD;
    const __half* Kbh = K + (size_t)bh * SS * DD;
    const __half* Vbh = V + (size_t)bh * SS * DD;

    // load Q tile (128 x 64 halves)
    {
        const int r = tid >> 1;
        const int ch = (tid & 1) * 32;
        const uint4* src = reinterpret_cast<const uint4*>(Qbh + (size_t)(q0 + r) * DD + ch);
        char* dst = sm + QS_OFF + r * FROWB + ch * 2;
        reinterpret_cast<uint4*>(dst)[0] = src[0];
        reinterpret_cast<uint4*>(dst)[1] = src[1];
        reinterpret_cast<uint4*>(dst)[2] = src[2];
        reinterpret_cast<uint4*>(dst)[3] = src[3];
    }
    __syncthreads();

    // hoisted Q fragments
    const int lr = lane & 7;
    const int aRow = warpM + lr + ((lane >> 3) & 1) * 8;
    const int aCb  = ((lane >> 4) & 1) * 16;
    uint32_t qf[4][4];
    #pragma unroll
    for (int ks = 0; ks < 4; ks++)
        LDSM_X4(qf[ks], sb + QS_OFF + (uint32_t)(aRow * FROWB + ks * 32 + aCb));

    // K/V loader: 4 threads/row, 16 halves each
    const int lrow = tid >> 2;
    const int lcb = (tid & 3) * 32;
    uint4 kr0, kr1, vr0, vr1;
    {
        const uint4* ksrc = reinterpret_cast<const uint4*>(
            reinterpret_cast<const char*>(Kbh + (size_t)lrow * DD) + lcb);
        kr0 = ksrc[0]; kr1 = ksrc[1];
        const uint4* vsrc = reinterpret_cast<const uint4*>(
            reinterpret_cast<const char*>(Vbh + (size_t)lrow * DD) + lcb);
        vr0 = vsrc[0]; vr1 = vsrc[1];
    }

    float m0 = -1e30f, m1 = -1e30f, l0 = 0.0f, l1 = 0.0f;
    float o[8][4];
    #pragma unroll
    for (int d8 = 0; d8 < 8; d8++)
        #pragma unroll
        for (int r = 0; r < 4; r++) o[d8][r] = 0.0f;

    const int bRowK = lr + ((lane >> 4) & 1) * 8;
    const int bCbK  = ((lane >> 3) & 1) * 16;
    const int vRowB = lr + ((lane >> 3) & 1) * 8;
    const int vCbB  = ((lane >> 4) & 1) * 16;

    for (int kt = 0; kt < 32; kt++) {
        if (kt) __syncthreads();
        {
            char* kd = sm + KS_OFF + lrow * FROWB + lcb;
            reinterpret_cast<uint4*>(kd)[0] = kr0;
            reinterpret_cast<uint4*>(kd)[1] = kr1;
            char* vd = sm + VS_OFF + lrow * FROWB + lcb;
            reinterpret_cast<uint4*>(vd)[0] = vr0;
            reinterpret_cast<uint4*>(vd)[1] = vr1;
        }
        __syncthreads();
        if (kt < 31) {
            const int krow = (kt + 1) * 64 + lrow;
            const uint4* ksrc = reinterpret_cast<const uint4*>(
                reinterpret_cast<const char*>(Kbh + (size_t)krow * DD) + lcb);
            kr0 = ksrc[0]; kr1 = ksrc[1];
            const uint4* vsrc = reinterpret_cast<const uint4*>(
                reinterpret_cast<const char*>(Vbh + (size_t)krow * DD) + lcb);
            vr0 = vsrc[0]; vr1 = vsrc[1];
        }

        // ---- QK^T ----
        float sc[8][4];
        #pragma unroll
        for (int nb = 0; nb < 8; nb++)
            #pragma unroll
            for (int r = 0; r < 4; r++) sc[nb][r] = 0.0f;
        #pragma unroll
        for (int ks = 0; ks < 4; ks++) {
            #pragma unroll
            for (int ng2 = 0; ng2 < 4; ng2++) {
                uint32_t kf[4];
                LDSM_X4(kf, sb + KS_OFF +
                        (uint32_t)((ng2 * 16 + bRowK) * FROWB + ks * 32 + bCbK));
                mma16816h(sc[2 * ng2 + 0], qf[ks], kf[0], kf[1]);
                mma16816h(sc[2 * ng2 + 1], qf[ks], kf[2], kf[3]);
            }
        }

        // ---- online softmax ----
        float mx0 = sc[0][0], mx1 = sc[0][2];
        #pragma unroll
        for (int nb = 0; nb < 8; nb++) {
            mx0 = fmaxf(mx0, fmaxf(sc[nb][0], sc[nb][1]));
            mx1 = fmaxf(mx1, fmaxf(sc[nb][2], sc[nb][3]));
        }
        mx0 = fmaxf(mx0, __shfl_xor_sync(0xffffffffu, mx0, 1));
        mx0 = fmaxf(mx0, __shfl_xor_sync(0xffffffffu, mx0, 2));
        mx1 = fmaxf(mx1, __shfl_xor_sync(0xffffffffu, mx1, 1));
        mx1 = fmaxf(mx1, __shfl_xor_sync(0xffffffffu, mx1, 2));
        const float mn0 = fmaxf(m0, mx0);
        const float mn1 = fmaxf(m1, mx1);
        const float c0 = exp2f(m0 - mn0);
        const float c1 = exp2f(m1 - mn1);
        m0 = mn0; m1 = mn1;

        float s0 = 0.0f, s1 = 0.0f;
        uint32_t pa0[8], pa1[8];
        #pragma unroll
        for (int nb = 0; nb < 8; nb++) {
            float p00 = exp2f(sc[nb][0] - mn0);
            float p01 = exp2f(sc[nb][1] - mn0);
            float p10 = exp2f(sc[nb][2] - mn1);
            float p11 = exp2f(sc[nb][3] - mn1);
            s0 += p00 + p01;
            s1 += p10 + p11;
            __half2 h0 = __floats2half2_rn(p00, p01);
            __half2 h1 = __floats2half2_rn(p10, p11);
            pa0[nb] = *reinterpret_cast<uint32_t*>(&h0);
            pa1[nb] = *reinterpret_cast<uint32_t*>(&h1);
        }
        l0 = l0 * c0 + s0;
        l1 = l1 * c1 + s1;
        #pragma unroll
        for (int d8 = 0; d8 < 8; d8++) {
            o[d8][0] *= c0; o[d8][1] *= c0;
            o[d8][2] *= c1; o[d8][3] *= c1;
        }

        // ---- P @ V ----
        #pragma unroll
        for (int ks = 0; ks < 4; ks++) {
            uint32_t pf[4] = {pa0[2 * ks], pa1[2 * ks], pa0[2 * ks + 1], pa1[2 * ks + 1]};
            #pragma unroll
            for (int dg2 = 0; dg2 < 4; dg2++) {
                uint32_t vf[4];
                LDSM_T_X4(vf, sb + VS_OFF +
                          (uint32_t)((ks * 16 + vRowB) * FROWB + dg2 * 32 + vCbB));
                mma16816h(o[2 * dg2 + 0], pf, vf[0], vf[1]);
                mma16816h(o[2 * dg2 + 1], pf, vf[2], vf[3]);
            }
        }
    }

    // ---- finalize: normalize, store fp16 ctx ----
    l0 += __shfl_xor_sync(0xffffffffu, l0, 1);
    l0 += __shfl_xor_sync(0xffffffffu, l0, 2);
    l1 += __shfl_xor_sync(0xffffffffu, l1, 1);
    l1 += __shfl_xor_sync(0xffffffffu, l1, 2);
    const float i0 = 1.0f / l0;
    const float i1 = 1.0f / l1;

    const int b = bh >> 4;
    const int h = bh & 15;
    const int g = lane >> 2;
    const int t2 = (lane & 3) * 2;
    const int r0 = q0 + warpM + g;
    __half* d0 = ctx + ((size_t)(b * SS + r0)) * EE + h * DD;
    __half* d1 = ctx + ((size_t)(b * SS + r0 + 8)) * EE + h * DD;
    #pragma unroll
    for (int d8 = 0; d8 < 8; d8++) {
        *reinterpret_cast<__half2*>(d0 + d8 * 8 + t2) =
            __floats2half2_rn(o[d8][0] * i0, o[d8][1] * i0);
        *reinterpret_cast<__half2*>(d1 + d8 * 8 + t2) =
            __floats2half2_rn(o[d8][2] * i1, o[d8][3] * i1);
    }
}

// ---------------- launch ----------------------------------------------------
extern "C" void kernel_launch(void* const* d_in, const int* in_sizes, int n_in,
                              void* d_out, int out_size)
{
    const float* x  = (const float*)d_in[0];
    const float* Wq = (const float*)d_in[1];
    const float* bq = (const float*)d_in[2];
    const float* Wk = (const float*)d_in[3];
    const float* bk = (const float*)d_in[4];
    const float* Wv = (const float*)d_in[5];
    const float* bv = (const float*)d_in[6];
    const float* Wo = (const float*)d_in[7];
    const float* bo = (const float*)d_in[8];
    float* out = (float*)d_out;

    __half *xh, *Wqh, *Wkh, *Wvh, *Woh, *Qp, *Kp, *Vp, *Cp;
    cudaGetSymbolAddress((void**)&xh,  g_xh);
    cudaGetSymbolAddress((void**)&Wqh, g_Wqh);
    cudaGetSymbolAddress((void**)&Wkh, g_Wkh);
    cudaGetSymbolAddress((void**)&Wvh, g_Wvh);
    cudaGetSymbolAddress((void**)&Woh, g_Woh);
    cudaGetSymbolAddress((void**)&Qp,  g_Qh);
    cudaGetSymbolAddress((void**)&Kp,  g_Kh);
    cudaGetSymbolAddress((void**)&Vp,  g_Vh);
    cudaGetSymbolAddress((void**)&Cp,  g_ctxh);

    cudaFuncSetAttribute(gemm_mma_kernel,
                         cudaFuncAttributeMaxDynamicSharedMemorySize, GSMEM_TOTAL);

    // ---- convert inputs to fp16 ----
    const int NW = EE * EE;          // 1M
    const int NX = MM * EE;          // 4M
    cvt_f2h_kernel<<<NX / (256 * 8), 256>>>(x,  xh,  NX);
    cvt_f2h_kernel<<<NW / (256 * 8), 256>>>(Wq, Wqh, NW);
    cvt_f2h_kernel<<<NW / (256 * 8), 256>>>(Wk, Wkh, NW);
    cvt_f2h_kernel<<<NW / (256 * 8), 256>>>(Wv, Wvh, NW);
    cvt_f2h_kernel<<<NW / (256 * 8), 256>>>(Wo, Woh, NW);

    dim3 gemmGrid(EE / 128, MM / 128);   // (8, 32)

    // Q pre-scaled by 0.125 * log2(e) so softmax uses exp2 directly
    const float qscale = 0.18033688011112042f;
    gemm_mma_kernel<<<gemmGrid, 256, GSMEM_TOTAL>>>(xh, Wqh, bq, nullptr, Qp, 1, qscale);
    gemm_mma_kernel<<<gemmGrid, 256, GSMEM_TOTAL>>>(xh, Wkh, bk, nullptr, Kp, 1, 1.0f);
    gemm_mma_kernel<<<gemmGrid, 256, GSMEM_TOTAL>>>(xh, Wvh, bv, nullptr, Vp, 1, 1.0f);

    dim3 faGrid(SS / 128, BB * HH);      // (16, 32)
    flash_mma_kernel<<<faGrid, dim3(256)>>>(Qp, Kp, Vp, Cp);

    gemm_mma_kernel<<<gemmGrid, 256, GSMEM_TOTAL>>>(Cp, Woh, bo, out, nullptr, 0, 1.0f);
}

// round 14
// speedup vs baseline: 7.4203x; 1.0502x over previous
#include <cuda_runtime.h>
#include <cuda_bf16.h>
#include <cuda_fp16.h>
#include <cstdint>

// Problem constants
#define BB 2
#define SS 2048
#define EE 1024
#define HH 16
#define DD 64
#define MM (BB * SS)   // 4096

// ---------------- scratch (device globals; no allocation allowed) ----------
__device__ __half g_xh[MM * EE];             // fp16 copy of x [4096,1024]
__device__ __half g_Wqh[EE * EE];
__device__ __half g_Wkh[EE * EE];
__device__ __half g_Wvh[EE * EE];
__device__ __half g_Woh[EE * EE];
__device__ __half g_Qh[BB * HH * SS * DD];   // [b,h,s,d] fp16 (pre-scaled)
__device__ __half g_Kh[BB * HH * SS * DD];
__device__ __half g_Vh[BB * HH * SS * DD];
__device__ __half g_ctxh[BB * SS * EE];      // [b,s,e] fp16

// ======================= helpers ===========================================
__device__ __forceinline__ uint32_t smem_u32(const void* p) {
    uint32_t a;
    asm("{ .reg .u64 t; cvta.to.shared.u64 t, %1; cvt.u32.u64 %0, t; }" : "=r"(a) : "l"(p));
    return a;
}

#define CP_ASYNC16(saddr, gptr) \
    asm volatile("cp.async.cg.shared.global [%0], [%1], 16;" \
                 :: "r"(saddr), "l"(gptr) : "memory")
#define CP_COMMIT() asm volatile("cp.async.commit_group;" ::: "memory")
#define CP_WAIT0()  asm volatile("cp.async.wait_group 0;" ::: "memory")

#define LDSM_X4(r, addr) \
    asm volatile("ldmatrix.sync.aligned.m8n8.x4.shared.b16 {%0,%1,%2,%3}, [%4];" \
        : "=r"((r)[0]), "=r"((r)[1]), "=r"((r)[2]), "=r"((r)[3]) : "r"(addr))

#define LDSM_T_X4(r, addr) \
    asm volatile("ldmatrix.sync.aligned.m8n8.x4.trans.shared.b16 {%0,%1,%2,%3}, [%4];" \
        : "=r"((r)[0]), "=r"((r)[1]), "=r"((r)[2]), "=r"((r)[3]) : "r"(addr))

__device__ __forceinline__ void mma16816h(float* c, const uint32_t* a,
                                          uint32_t b0, uint32_t b1) {
    asm volatile(
        "mma.sync.aligned.m16n8k16.row.col.f32.f16.f16.f32 "
        "{%0,%1,%2,%3}, {%4,%5,%6,%7}, {%8,%9}, {%0,%1,%2,%3};"
        : "+f"(c[0]), "+f"(c[1]), "+f"(c[2]), "+f"(c[3])
        : "r"(a[0]), "r"(a[1]), "r"(a[2]), "r"(a[3]), "r"(b0), "r"(b1));
}

// ================ fp32 -> fp16 convert pass (8 elts/thread) =================
__global__ __launch_bounds__(256) void cvt_f2h_kernel(
    const float* __restrict__ src, __half* __restrict__ dst, int n)
{
    const int i = (blockIdx.x * 256 + threadIdx.x) * 8;
    if (i >= n) return;
    float4 a = *reinterpret_cast<const float4*>(src + i);
    float4 b = *reinterpret_cast<const float4*>(src + i + 4);
    __half2 h0 = __floats2half2_rn(a.x, a.y);
    __half2 h1 = __floats2half2_rn(a.z, a.w);
    __half2 h2 = __floats2half2_rn(b.x, b.y);
    __half2 h3 = __floats2half2_rn(b.z, b.w);
    uint4 o;
    o.x = *reinterpret_cast<uint32_t*>(&h0);
    o.y = *reinterpret_cast<uint32_t*>(&h1);
    o.z = *reinterpret_cast<uint32_t*>(&h2);
    o.w = *reinterpret_cast<uint32_t*>(&h3);
    *reinterpret_cast<uint4*>(dst + i) = o;
}

// ============ mma.sync fp16 GEMM: C = A[M,K] @ W[N,K]^T + bias ==============
// All-fp16, cp.async double-buffered, one sync per k-stage.
// CTA tile 128x128, K-chunk 32, 256 threads (8 warps, 4x2 of 32x64).
// qkv_mode: z selects (W,bias,dst,scale); out_mode 0 writes float Cf.
#define ROWB 80
#define MAT_BYTES (128 * ROWB)        // 10240
#define STG_BYTES (2 * MAT_BYTES)     // 20480: Ah, Bh
#define GSMEM_TOTAL (2 * STG_BYTES)   // 40960

__global__ __launch_bounds__(256) void gemm_mma_kernel(
    const __half* __restrict__ A,
    const __half* __restrict__ W0,
    const __half* __restrict__ W1,
    const __half* __restrict__ W2,
    const float* __restrict__ b0p,
    const float* __restrict__ b1p,
    const float* __restrict__ b2p,
    float* __restrict__ Cf,
    __half* __restrict__ Ch0,
    __half* __restrict__ Ch1,
    __half* __restrict__ Ch2,
    int out_mode, float qscale)
{
    extern __shared__ __align__(16) char ds[];
    const int tid = threadIdx.x;
    const int wid = tid >> 5;
    const int lane = tid & 31;
    const int bm = blockIdx.y * 128;
    const int bn = blockIdx.x * 128;
    const int z = blockIdx.z;
    const int warpM = (wid & 3) * 32;
    const int warpN = (wid >> 2) * 64;

    const __half* W = (z == 0) ? W0 : (z == 1) ? W1 : W2;
    const float* bias = (z == 0) ? b0p : (z == 1) ? b1p : b2p;
    __half* Ch = (z == 0) ? Ch0 : (z == 1) ? Ch1 : Ch2;
    const float oscale = (z == 0) ? qscale : 1.0f;

    // loader: 2 threads per row, 16 consecutive k-halves per thread
    const int ldRow = tid >> 1;
    const int ldH = (tid & 1) * 16;
    const __half* Ap = A + (size_t)(bm + ldRow) * 1024 + ldH;
    const __half* Wp = W + (size_t)(bn + ldRow) * 1024 + ldH;

    const uint32_t sbase = smem_u32(ds);
    const uint32_t stOff = (uint32_t)(ldRow * ROWB + ldH * 2);  // bytes

    float acc[2][8][4];
    #pragma unroll
    for (int mt = 0; mt < 2; mt++)
        #pragma unroll
        for (int nb = 0; nb < 8; nb++)
            #pragma unroll
            for (int r = 0; r < 4; r++) acc[mt][nb][r] = 0.0f;

    // ---- prologue: cp.async stage 0 ----
    {
        const uint32_t sA = sbase;
        CP_ASYNC16(sA + stOff, Ap);
        CP_ASYNC16(sA + stOff + 16, Ap + 8);
        CP_ASYNC16(sA + MAT_BYTES + stOff, Wp);
        CP_ASYNC16(sA + MAT_BYTES + stOff + 16, Wp + 8);
        CP_COMMIT();
    }
    CP_WAIT0();
    __syncthreads();

    // ldmatrix address components
    const int lr = lane & 7;
    const int aRow = warpM + lr + ((lane >> 3) & 1) * 8;
    const int aKb  = ((lane >> 4) & 1) * 16;
    const int bRow = warpN + lr + ((lane >> 4) & 1) * 8;
    const int bKb  = ((lane >> 3) & 1) * 16;

    for (int s = 0; s < 32; s++) {
        const int buf = s & 1;

        if (s < 31) {
            const int kn = (s + 1) * 32;
            const uint32_t sN = sbase + ((s + 1) & 1) * STG_BYTES;
            CP_ASYNC16(sN + stOff, Ap + kn);
            CP_ASYNC16(sN + stOff + 16, Ap + kn + 8);
            CP_ASYNC16(sN + MAT_BYTES + stOff, Wp + kn);
            CP_ASYNC16(sN + MAT_BYTES + stOff + 16, Wp + kn + 8);
            CP_COMMIT();
        }

        // ---- compute stage s ----
        const uint32_t sA = sbase + buf * STG_BYTES;
        const uint32_t sB = sA + MAT_BYTES;
        #pragma unroll
        for (int kt = 0; kt < 2; kt++) {
            uint32_t af[2][4];
            #pragma unroll
            for (int mt = 0; mt < 2; mt++)
                LDSM_X4(af[mt], sA + (uint32_t)((aRow + mt * 16) * ROWB + kt * 32 + aKb));
            uint32_t bf[4][4];
            #pragma unroll
            for (int nb2 = 0; nb2 < 4; nb2++)
                LDSM_X4(bf[nb2], sB + (uint32_t)((bRow + nb2 * 16) * ROWB + kt * 32 + bKb));
            #pragma unroll
            for (int mt = 0; mt < 2; mt++) {
                #pragma unroll
                for (int nb2 = 0; nb2 < 4; nb2++) {
                    mma16816h(acc[mt][2 * nb2 + 0], af[mt], bf[nb2][0], bf[nb2][1]);
                    mma16816h(acc[mt][2 * nb2 + 1], af[mt], bf[nb2][2], bf[nb2][3]);
                }
            }
        }

        if (s < 31) {
            CP_WAIT0();
            __syncthreads();
        }
    }

    // ---- epilogue ----
    const int gRow = lane >> 2;
    const int gCol = (lane & 3) * 2;
    #pragma unroll
    for (int mt = 0; mt < 2; mt++) {
        #pragma unroll
        for (int half_ = 0; half_ < 2; half_++) {
            const int m = bm + warpM + mt * 16 + gRow + half_ * 8;
            const int b = m >> 11;
            const int srow = m & 2047;
            #pragma unroll
            for (int nb = 0; nb < 8; nb++) {
                const int n = bn + warpN + nb * 8 + gCol;
                float vx = acc[mt][nb][half_ * 2 + 0] + bias[n];
                float vy = acc[mt][nb][half_ * 2 + 1] + bias[n + 1];
                if (out_mode == 1) {
                    const int h = n >> 6;
                    const int d = n & 63;
                    __half2 hv = __floats2half2_rn(vx * oscale, vy * oscale);
                    *reinterpret_cast<__half2*>(
                        Ch + (((size_t)(b * HH + h) << 11) + srow) * DD + d) = hv;
                } else {
                    *reinterpret_cast<float2*>(Cf + (size_t)m * EE + n) =
                        make_float2(vx, vy);
                }
            }
        }
    }
}

// ============ Flash attention via mma.sync fp16 =============================
// CTA: 128 q-rows of one (b,h); 8 warps x m16. K-tiles of 64 keys.
// cp.async double-buffered K/V; one sync per tile.
// Q pre-scaled by 0.125*log2(e) so p = exp2(s - m) directly. ctx out fp16.
#define FROWB 144                       // 64 halves (128B) + 16B pad
#define QS_BYTES (128 * FROWB)          // 18432
#define KV_HALF (64 * FROWB)            // 9216 (one K or V tile)
#define KV_STG (2 * KV_HALF)            // 18432 per stage (K + V)
#define FSMEM  (QS_BYTES + 2 * KV_STG)  // 55296

__global__ __launch_bounds__(256) void flash_mma_kernel(
    const __half* __restrict__ Q,
    const __half* __restrict__ K,
    const __half* __restrict__ V,
    __half* __restrict__ ctx)           // [b,s,e] fp16
{
    __shared__ __align__(16) char sm[FSMEM];
    const int bh = blockIdx.y;
    const int q0 = blockIdx.x * 128;
    const int tid = threadIdx.x;
    const int wid = tid >> 5;
    const int lane = tid & 31;
    const int warpM = wid * 16;
    const uint32_t sb = smem_u32(sm);

    const __half* Qbh = Q + (size_t)bh * SS * DD;
    const __half* Kbh = K + (size_t)bh * SS * DD;
    const __half* Vbh = V + (size_t)bh * SS * DD;

    // K/V loader mapping: 4 threads/row, 32B each
    const int lrow = tid >> 2;
    const int lcb = (tid & 3) * 32;
    const uint32_t kvb0 = sb + QS_BYTES;            // stage 0 base
    const uint32_t kvb1 = sb + QS_BYTES + KV_STG;   // stage 1 base

    // load Q tile (128 x 64 halves) with regular stores
    {
        const int r = tid >> 1;
        const int ch = (tid & 1) * 32;
        const uint4* src = reinterpret_cast<const uint4*>(Qbh + (size_t)(q0 + r) * DD + ch);
        char* dst = sm + r * FROWB + ch * 2;
        reinterpret_cast<uint4*>(dst)[0] = src[0];
        reinterpret_cast<uint4*>(dst)[1] = src[1];
        reinterpret_cast<uint4*>(dst)[2] = src[2];
        reinterpret_cast<uint4*>(dst)[3] = src[3];
    }

    // prologue: cp.async K/V tile 0 -> stage 0
    {
        const uint32_t kd = kvb0 + (uint32_t)(lrow * FROWB + lcb);
        const char* kg = reinterpret_cast<const char*>(Kbh + (size_t)lrow * DD) + lcb;
        CP_ASYNC16(kd, kg);
        CP_ASYNC16(kd + 16, kg + 16);
        const uint32_t vd = kd + KV_HALF;
        const char* vg = reinterpret_cast<const char*>(Vbh + (size_t)lrow * DD) + lcb;
        CP_ASYNC16(vd, vg);
        CP_ASYNC16(vd + 16, vg + 16);
        CP_COMMIT();
    }
    CP_WAIT0();
    __syncthreads();

    // hoisted Q fragments
    const int lr = lane & 7;
    const int aRow = warpM + lr + ((lane >> 3) & 1) * 8;
    const int aCb  = ((lane >> 4) & 1) * 16;
    uint32_t qf[4][4];
    #pragma unroll
    for (int ks = 0; ks < 4; ks++)
        LDSM_X4(qf[ks], sb + (uint32_t)(aRow * FROWB + ks * 32 + aCb));

    float m0 = -1e30f, m1 = -1e30f, l0 = 0.0f, l1 = 0.0f;
    float o[8][4];
    #pragma unroll
    for (int d8 = 0; d8 < 8; d8++)
        #pragma unroll
        for (int r = 0; r < 4; r++) o[d8][r] = 0.0f;

    const int bRowK = lr + ((lane >> 4) & 1) * 8;
    const int bCbK  = ((lane >> 3) & 1) * 16;
    const int vRowB = lr + ((lane >> 3) & 1) * 8;
    const int vCbB  = ((lane >> 4) & 1) * 16;

    for (int kt = 0; kt < 32; kt++) {
        const uint32_t kvb = (kt & 1) ? kvb1 : kvb0;

        if (kt < 31) {
            const int krow = (kt + 1) * 64 + lrow;
            const uint32_t nb = ((kt + 1) & 1) ? kvb1 : kvb0;
            const uint32_t kd = nb + (uint32_t)(lrow * FROWB + lcb);
            const char* kg = reinterpret_cast<const char*>(Kbh + (size_t)krow * DD) + lcb;
            CP_ASYNC16(kd, kg);
            CP_ASYNC16(kd + 16, kg + 16);
            const uint32_t vd = kd + KV_HALF;
            const char* vg = reinterpret_cast<const char*>(Vbh + (size_t)krow * DD) + lcb;
            CP_ASYNC16(vd, vg);
            CP_ASYNC16(vd + 16, vg + 16);
            CP_COMMIT();
        }

        // ---- QK^T ----
        float sc[8][4];
        #pragma unroll
        for (int nb = 0; nb < 8; nb++)
            #pragma unroll
            for (int r = 0; r < 4; r++) sc[nb][r] = 0.0f;
        #pragma unroll
        for (int ks = 0; ks < 4; ks++) {
            #pragma unroll
            for (int ng2 = 0; ng2 < 4; ng2++) {
                uint32_t kf[4];
                LDSM_X4(kf, kvb + (uint32_t)((ng2 * 16 + bRowK) * FROWB + ks * 32 + bCbK));
                mma16816h(sc[2 * ng2 + 0], qf[ks], kf[0], kf[1]);
                mma16816h(sc[2 * ng2 + 1], qf[ks], kf[2], kf[3]);
            }
        }

        // ---- online softmax ----
        float mx0 = sc[0][0], mx1 = sc[0][2];
        #pragma unroll
        for (int nb = 0; nb < 8; nb++) {
            mx0 = fmaxf(mx0, fmaxf(sc[nb][0], sc[nb][1]));
            mx1 = fmaxf(mx1, fmaxf(sc[nb][2], sc[nb][3]));
        }
        mx0 = fmaxf(mx0, __shfl_xor_sync(0xffffffffu, mx0, 1));
        mx0 = fmaxf(mx0, __shfl_xor_sync(0xffffffffu, mx0, 2));
        mx1 = fmaxf(mx1, __shfl_xor_sync(0xffffffffu, mx1, 1));
        mx1 = fmaxf(mx1, __shfl_xor_sync(0xffffffffu, mx1, 2));
        const float mn0 = fmaxf(m0, mx0);
        const float mn1 = fmaxf(m1, mx1);
        const float c0 = exp2f(m0 - mn0);
        const float c1 = exp2f(m1 - mn1);
        m0 = mn0; m1 = mn1;

        float s0 = 0.0f, s1 = 0.0f;
        uint32_t pa0[8], pa1[8];
        #pragma unroll
        for (int nb = 0; nb < 8; nb++) {
            float p00 = exp2f(sc[nb][0] - mn0);
            float p01 = exp2f(sc[nb][1] - mn0);
            float p10 = exp2f(sc[nb][2] - mn1);
            float p11 = exp2f(sc[nb][3] - mn1);
            s0 += p00 + p01;
            s1 += p10 + p11;
            __half2 h0 = __floats2half2_rn(p00, p01);
            __half2 h1 = __floats2half2_rn(p10, p11);
            pa0[nb] = *reinterpret_cast<uint32_t*>(&h0);
            pa1[nb] = *reinterpret_cast<uint32_t*>(&h1);
        }
        l0 = l0 * c0 + s0;
        l1 = l1 * c1 + s1;
        #pragma unroll
        for (int d8 = 0; d8 < 8; d8++) {
            o[d8][0] *= c0; o[d8][1] *= c0;
            o[d8][2] *= c1; o[d8][3] *= c1;
        }

        // ---- P @ V ----
        const uint32_t vbase = kvb + KV_HALF;
        #pragma unroll
        for (int ks = 0; ks < 4; ks++) {
            uint32_t pf[4] = {pa0[2 * ks], pa1[2 * ks], pa0[2 * ks + 1], pa1[2 * ks + 1]};
            #pragma unroll
            for (int dg2 = 0; dg2 < 4; dg2++) {
                uint32_t vf[4];
                LDSM_T_X4(vf, vbase + (uint32_t)((ks * 16 + vRowB) * FROWB + dg2 * 32 + vCbB));
                mma16816h(o[2 * dg2 + 0], pf, vf[0], vf[1]);
                mma16816h(o[2 * dg2 + 1], pf, vf[2], vf[3]);
            }
        }

        if (kt < 31) {
            CP_WAIT0();
            __syncthreads();
        }
    }

    // ---- finalize: normalize, store fp16 ctx ----
    l0 += __shfl_xor_sync(0xffffffffu, l0, 1);
    l0 += __shfl_xor_sync(0xffffffffu, l0, 2);
    l1 += __shfl_xor_sync(0xffffffffu, l1, 1);
    l1 += __shfl_xor_sync(0xffffffffu, l1, 2);
    const float i0 = 1.0f / l0;
    const float i1 = 1.0f / l1;

    const int b = bh >> 4;
    const int h = bh & 15;
    const int g = lane >> 2;
    const int t2 = (lane & 3) * 2;
    const int r0 = q0 + warpM + g;
    __half* d0 = ctx + ((size_t)(b * SS + r0)) * EE + h * DD;
    __half* d1 = ctx + ((size_t)(b * SS + r0 + 8)) * EE + h * DD;
    #pragma unroll
    for (int d8 = 0; d8 < 8; d8++) {
        *reinterpret_cast<__half2*>(d0 + d8 * 8 + t2) =
            __floats2half2_rn(o[d8][0] * i0, o[d8][1] * i0);
        *reinterpret_cast<__half2*>(d1 + d8 * 8 + t2) =
            __floats2half2_rn(o[d8][2] * i1, o[d8][3] * i1);
    }
}

// ---------------- launch ----------------------------------------------------
extern "C" void kernel_launch(void* const* d_in, const int* in_sizes, int n_in,
                              void* d_out, int out_size)
{
    const float* x  = (const float*)d_in[0];
    const float* Wq = (const float*)d_in[1];
    const float* bq = (const float*)d_in[2];
    const float* Wk = (const float*)d_in[3];
    const float* bk = (const float*)d_in[4];
    const float* Wv = (const float*)d_in[5];
    const float* bv = (const float*)d_in[6];
    const float* Wo = (const float*)d_in[7];
    const float* bo = (const float*)d_in[8];
    float* out = (float*)d_out;

    __half *xh, *Wqh, *Wkh, *Wvh, *Woh, *Qp, *Kp, *Vp, *Cp;
    cudaGetSymbolAddress((void**)&xh,  g_xh);
    cudaGetSymbolAddress((void**)&Wqh, g_Wqh);
    cudaGetSymbolAddress((void**)&Wkh, g_Wkh);
    cudaGetSymbolAddress((void**)&Wvh, g_Wvh);
    cudaGetSymbolAddress((void**)&Woh, g_Woh);
    cudaGetSymbolAddress((void**)&Qp,  g_Qh);
    cudaGetSymbolAddress((void**)&Kp,  g_Kh);
    cudaGetSymbolAddress((void**)&Vp,  g_Vh);
    cudaGetSymbolAddress((void**)&Cp,  g_ctxh);

    cudaFuncSetAttribute(gemm_mma_kernel,
                         cudaFuncAttributeMaxDynamicSharedMemorySize, GSMEM_TOTAL);

    // ---- convert inputs to fp16 ----
    const int NW = EE * EE;          // 1M
    const int NX = MM * EE;          // 4M
    cvt_f2h_kernel<<<NX / (256 * 8), 256>>>(x,  xh,  NX);
    cvt_f2h_kernel<<<NW / (256 * 8), 256>>>(Wq, Wqh, NW);
    cvt_f2h_kernel<<<NW / (256 * 8), 256>>>(Wk, Wkh, NW);
    cvt_f2h_kernel<<<NW / (256 * 8), 256>>>(Wv, Wvh, NW);
    cvt_f2h_kernel<<<NW / (256 * 8), 256>>>(Wo, Woh, NW);

    // Q pre-scaled by 0.125 * log2(e) so softmax uses exp2 directly
    const float qscale = 0.18033688011112042f;

    // ---- merged Q/K/V projections (z selects target) ----
    dim3 qkvGrid(EE / 128, MM / 128, 3);   // (8, 32, 3)
    gemm_mma_kernel<<<qkvGrid, 256, GSMEM_TOTAL>>>(
        xh, Wqh, Wkh, Wvh, bq, bk, bv, nullptr, Qp, Kp, Vp, 1, qscale);

    // ---- attention ----
    dim3 faGrid(SS / 128, BB * HH);        // (16, 32)
    flash_mma_kernel<<<faGrid, dim3(256)>>>(Qp, Kp, Vp, Cp);

    // ---- output projection ----
    dim3 oGrid(EE / 128, MM / 128, 1);
    gemm_mma_kernel<<<oGrid, 256, GSMEM_TOTAL>>>(
        Cp, Woh, Woh, Woh, bo, bo, bo, out, nullptr, nullptr, nullptr, 0, 1.0f);
}

// round 15
// speedup vs baseline: 8.1756x; 1.1018x over previous
#include <cuda_runtime.h>
#include <cuda_bf16.h>
#include <cuda_fp16.h>
#include <cstdint>

// Problem constants
#define BB 2
#define SS 2048
#define EE 1024
#define HH 16
#define DD 64
#define MM (BB * SS)   // 4096

// ---------------- scratch (device globals; no allocation allowed) ----------
__device__ __half g_xh[MM * EE];             // fp16 copy of x [4096,1024]
__device__ __half g_Wqh[EE * EE];
__device__ __half g_Wkh[EE * EE];
__device__ __half g_Wvh[EE * EE];
__device__ __half g_Woh[EE * EE];
__device__ __half g_Qh[BB * HH * SS * DD];   // [b,h,s,d] fp16 (pre-scaled)
__device__ __half g_Kh[BB * HH * SS * DD];
__device__ __half g_Vh[BB * HH * SS * DD];
__device__ __half g_ctxh[BB * SS * EE];      // [b,s,e] fp16

// ======================= helpers ===========================================
__device__ __forceinline__ uint32_t smem_u32(const void* p) {
    uint32_t a;
    asm("{ .reg .u64 t; cvta.to.shared.u64 t, %1; cvt.u32.u64 %0, t; }" : "=r"(a) : "l"(p));
    return a;
}

#define CP_ASYNC16(saddr, gptr) \
    asm volatile("cp.async.cg.shared.global [%0], [%1], 16;" \
                 :: "r"(saddr), "l"(gptr) : "memory")
#define CP_COMMIT() asm volatile("cp.async.commit_group;" ::: "memory")
#define CP_WAIT0()  asm volatile("cp.async.wait_group 0;" ::: "memory")
#define CP_WAIT1()  asm volatile("cp.async.wait_group 1;" ::: "memory")
#define CP_WAIT2()  asm volatile("cp.async.wait_group 2;" ::: "memory")

#define LDSM_X4(r, addr) \
    asm volatile("ldmatrix.sync.aligned.m8n8.x4.shared.b16 {%0,%1,%2,%3}, [%4];" \
        : "=r"((r)[0]), "=r"((r)[1]), "=r"((r)[2]), "=r"((r)[3]) : "r"(addr))

#define LDSM_T_X4(r, addr) \
    asm volatile("ldmatrix.sync.aligned.m8n8.x4.trans.shared.b16 {%0,%1,%2,%3}, [%4];" \
        : "=r"((r)[0]), "=r"((r)[1]), "=r"((r)[2]), "=r"((r)[3]) : "r"(addr))

__device__ __forceinline__ void mma16816h(float* c, const uint32_t* a,
                                          uint32_t b0, uint32_t b1) {
    asm volatile(
        "mma.sync.aligned.m16n8k16.row.col.f32.f16.f16.f32 "
        "{%0,%1,%2,%3}, {%4,%5,%6,%7}, {%8,%9}, {%0,%1,%2,%3};"
        : "+f"(c[0]), "+f"(c[1]), "+f"(c[2]), "+f"(c[3])
        : "r"(a[0]), "r"(a[1]), "r"(a[2]), "r"(a[3]), "r"(b0), "r"(b1));
}

__device__ __forceinline__ uint32_t ex2_h2(uint32_t u) {
    asm("ex2.approx.f16x2 %0, %1;" : "=r"(u) : "r"(u));
    return u;
}

// ================ fp32 -> fp16 convert passes ===============================
__global__ __launch_bounds__(256) void cvt_f2h_kernel(
    const float* __restrict__ src, __half* __restrict__ dst, int n)
{
    const int i = (blockIdx.x * 256 + threadIdx.x) * 8;
    if (i >= n) return;
    float4 a = *reinterpret_cast<const float4*>(src + i);
    float4 b = *reinterpret_cast<const float4*>(src + i + 4);
    __half2 h0 = __floats2half2_rn(a.x, a.y);
    __half2 h1 = __floats2half2_rn(a.z, a.w);
    __half2 h2 = __floats2half2_rn(b.x, b.y);
    __half2 h3 = __floats2half2_rn(b.z, b.w);
    uint4 o;
    o.x = *reinterpret_cast<uint32_t*>(&h0);
    o.y = *reinterpret_cast<uint32_t*>(&h1);
    o.z = *reinterpret_cast<uint32_t*>(&h2);
    o.w = *reinterpret_cast<uint32_t*>(&h3);
    *reinterpret_cast<uint4*>(dst + i) = o;
}

__global__ __launch_bounds__(256) void cvt_w_kernel(
    const float* __restrict__ s0, const float* __restrict__ s1,
    const float* __restrict__ s2, const float* __restrict__ s3,
    __half* __restrict__ d0, __half* __restrict__ d1,
    __half* __restrict__ d2, __half* __restrict__ d3)
{
    const int z = blockIdx.y;
    const float* src = (z == 0) ? s0 : (z == 1) ? s1 : (z == 2) ? s2 : s3;
    __half* dst = (z == 0) ? d0 : (z == 1) ? d1 : (z == 2) ? d2 : d3;
    const int i = (blockIdx.x * 256 + threadIdx.x) * 8;
    float4 a = *reinterpret_cast<const float4*>(src + i);
    float4 b = *reinterpret_cast<const float4*>(src + i + 4);
    __half2 h0 = __floats2half2_rn(a.x, a.y);
    __half2 h1 = __floats2half2_rn(a.z, a.w);
    __half2 h2 = __floats2half2_rn(b.x, b.y);
    __half2 h3 = __floats2half2_rn(b.z, b.w);
    uint4 o;
    o.x = *reinterpret_cast<uint32_t*>(&h0);
    o.y = *reinterpret_cast<uint32_t*>(&h1);
    o.z = *reinterpret_cast<uint32_t*>(&h2);
    o.w = *reinterpret_cast<uint32_t*>(&h3);
    *reinterpret_cast<uint4*>(dst + i) = o;
}

// ============ mma.sync fp16 GEMM: C = A[M,K] @ W[N,K]^T + bias ==============
// All-fp16, 4-stage cp.async pipeline (wait_group 2), one sync per k-stage.
// CTA tile 128x128, K-chunk 32, 256 threads (8 warps, 4x2 of 32x64).
#define ROWB 80
#define MAT_BYTES (128 * ROWB)        // 10240
#define STG_BYTES (2 * MAT_BYTES)     // 20480: Ah, Bh
#define GSTAGES 4
#define GSMEM_TOTAL (GSTAGES * STG_BYTES)   // 81920

__global__ __launch_bounds__(256) void gemm_mma_kernel(
    const __half* __restrict__ A,
    const __half* __restrict__ W0,
    const __half* __restrict__ W1,
    const __half* __restrict__ W2,
    const float* __restrict__ b0p,
    const float* __restrict__ b1p,
    const float* __restrict__ b2p,
    float* __restrict__ Cf,
    __half* __restrict__ Ch0,
    __half* __restrict__ Ch1,
    __half* __restrict__ Ch2,
    int out_mode, float qscale)
{
    extern __shared__ __align__(16) char ds[];
    const int tid = threadIdx.x;
    const int wid = tid >> 5;
    const int lane = tid & 31;
    const int bm = blockIdx.y * 128;
    const int bn = blockIdx.x * 128;
    const int z = blockIdx.z;
    const int warpM = (wid & 3) * 32;
    const int warpN = (wid >> 2) * 64;

    const __half* W = (z == 0) ? W0 : (z == 1) ? W1 : W2;
    const float* bias = (z == 0) ? b0p : (z == 1) ? b1p : b2p;
    __half* Ch = (z == 0) ? Ch0 : (z == 1) ? Ch1 : Ch2;
    const float oscale = (z == 0) ? qscale : 1.0f;

    // loader: 2 threads per row, 16 consecutive k-halves per thread
    const int ldRow = tid >> 1;
    const int ldH = (tid & 1) * 16;
    const __half* Ap = A + (size_t)(bm + ldRow) * 1024 + ldH;
    const __half* Wp = W + (size_t)(bn + ldRow) * 1024 + ldH;

    const uint32_t sbase = smem_u32(ds);
    const uint32_t stOff = (uint32_t)(ldRow * ROWB + ldH * 2);  // bytes

    float acc[2][8][4];
    #pragma unroll
    for (int mt = 0; mt < 2; mt++)
        #pragma unroll
        for (int nb = 0; nb < 8; nb++)
            #pragma unroll
            for (int r = 0; r < 4; r++) acc[mt][nb][r] = 0.0f;

    // ---- prologue: issue stages 0..2 ----
    #pragma unroll
    for (int p = 0; p < 3; p++) {
        const uint32_t sN = sbase + p * STG_BYTES;
        const int kn = p * 32;
        CP_ASYNC16(sN + stOff, Ap + kn);
        CP_ASYNC16(sN + stOff + 16, Ap + kn + 8);
        CP_ASYNC16(sN + MAT_BYTES + stOff, Wp + kn);
        CP_ASYNC16(sN + MAT_BYTES + stOff + 16, Wp + kn + 8);
        CP_COMMIT();
    }

    // ldmatrix address components
    const int lr = lane & 7;
    const int aRow = warpM + lr + ((lane >> 3) & 1) * 8;
    const int aKb  = ((lane >> 4) & 1) * 16;
    const int bRow = warpN + lr + ((lane >> 4) & 1) * 8;
    const int bKb  = ((lane >> 3) & 1) * 16;

    for (int s = 0; s < 32; s++) {
        // wait for stage s, then sync (all warps done with stage s-1's buffer)
        if (s < 30) { CP_WAIT2(); }
        else if (s == 30) { CP_WAIT1(); }
        else { CP_WAIT0(); }
        __syncthreads();

        // issue stage s+3 (reuses buffer of stage s-1; safe after sync)
        if (s + 3 < 32) {
            const uint32_t sN = sbase + ((s + 3) & 3) * STG_BYTES;
            const int kn = (s + 3) * 32;
            CP_ASYNC16(sN + stOff, Ap + kn);
            CP_ASYNC16(sN + stOff + 16, Ap + kn + 8);
            CP_ASYNC16(sN + MAT_BYTES + stOff, Wp + kn);
            CP_ASYNC16(sN + MAT_BYTES + stOff + 16, Wp + kn + 8);
            CP_COMMIT();
        }

        // ---- compute stage s ----
        const uint32_t sA = sbase + (s & 3) * STG_BYTES;
        const uint32_t sB = sA + MAT_BYTES;
        #pragma unroll
        for (int kt = 0; kt < 2; kt++) {
            uint32_t af[2][4];
            #pragma unroll
            for (int mt = 0; mt < 2; mt++)
                LDSM_X4(af[mt], sA + (uint32_t)((aRow + mt * 16) * ROWB + kt * 32 + aKb));
            uint32_t bf[4][4];
            #pragma unroll
            for (int nb2 = 0; nb2 < 4; nb2++)
                LDSM_X4(bf[nb2], sB + (uint32_t)((bRow + nb2 * 16) * ROWB + kt * 32 + bKb));
            #pragma unroll
            for (int mt = 0; mt < 2; mt++) {
                #pragma unroll
                for (int nb2 = 0; nb2 < 4; nb2++) {
                    mma16816h(acc[mt][2 * nb2 + 0], af[mt], bf[nb2][0], bf[nb2][1]);
                    mma16816h(acc[mt][2 * nb2 + 1], af[mt], bf[nb2][2], bf[nb2][3]);
                }
            }
        }
    }

    // ---- epilogue ----
    const int gRow = lane >> 2;
    const int gCol = (lane & 3) * 2;
    #pragma unroll
    for (int mt = 0; mt < 2; mt++) {
        #pragma unroll
        for (int half_ = 0; half_ < 2; half_++) {
            const int m = bm + warpM + mt * 16 + gRow + half_ * 8;
            const int b = m >> 11;
            const int srow = m & 2047;
            #pragma unroll
            for (int nb = 0; nb < 8; nb++) {
                const int n = bn + warpN + nb * 8 + gCol;
                float vx = acc[mt][nb][half_ * 2 + 0] + bias[n];
                float vy = acc[mt][nb][half_ * 2 + 1] + bias[n + 1];
                if (out_mode == 1) {
                    const int h = n >> 6;
                    const int d = n & 63;
                    __half2 hv = __floats2half2_rn(vx * oscale, vy * oscale);
                    *reinterpret_cast<__half2*>(
                        Ch + (((size_t)(b * HH + h) << 11) + srow) * DD + d) = hv;
                } else {
                    *reinterpret_cast<float2*>(Cf + (size_t)m * EE + n) =
                        make_float2(vx, vy);
                }
            }
        }
    }
}

// ============ Flash attention via mma.sync fp16 =============================
// CTA: 128 q-rows of one (b,h); 8 warps x m16. K-tiles of 64 keys.
// cp.async double-buffered K/V; ex2.approx.f16x2 softmax; l-sum via ones-MMA.
#define FROWB 144                       // 64 halves (128B) + 16B pad
#define QS_BYTES (128 * FROWB)          // 18432
#define KV_HALF (64 * FROWB)            // 9216 (one K or V tile)
#define KV_STG (2 * KV_HALF)            // 18432 per stage (K + V)
#define FSMEM  (QS_BYTES + 2 * KV_STG)  // 55296

__global__ __launch_bounds__(256) void flash_mma_kernel(
    const __half* __restrict__ Q,
    const __half* __restrict__ K,
    const __half* __restrict__ V,
    __half* __restrict__ ctx)           // [b,s,e] fp16
{
    __shared__ __align__(16) char sm[FSMEM];
    const int bh = blockIdx.y;
    const int q0 = blockIdx.x * 128;
    const int tid = threadIdx.x;
    const int wid = tid >> 5;
    const int lane = tid & 31;
    const int warpM = wid * 16;
    const uint32_t sb = smem_u32(sm);

    const __half* Qbh = Q + (size_t)bh * SS * DD;
    const __half* Kbh = K + (size_t)bh * SS * DD;
    const __half* Vbh = V + (size_t)bh * SS * DD;

    // K/V loader mapping: 4 threads/row, 32B each
    const int lrow = tid >> 2;
    const int lcb = (tid & 3) * 32;
    const uint32_t kvb0 = sb + QS_BYTES;
    const uint32_t kvb1 = sb + QS_BYTES + KV_STG;

    // load Q tile (128 x 64 halves)
    {
        const int r = tid >> 1;
        const int ch = (tid & 1) * 32;
        const uint4* src = reinterpret_cast<const uint4*>(Qbh + (size_t)(q0 + r) * DD + ch);
        char* dst = sm + r * FROWB + ch * 2;
        reinterpret_cast<uint4*>(dst)[0] = src[0];
        reinterpret_cast<uint4*>(dst)[1] = src[1];
        reinterpret_cast<uint4*>(dst)[2] = src[2];
        reinterpret_cast<uint4*>(dst)[3] = src[3];
    }

    // prologue: cp.async K/V tile 0 -> stage 0
    {
        const uint32_t kd = kvb0 + (uint32_t)(lrow * FROWB + lcb);
        const char* kg = reinterpret_cast<const char*>(Kbh + (size_t)lrow * DD) + lcb;
        CP_ASYNC16(kd, kg);
        CP_ASYNC16(kd + 16, kg + 16);
        const uint32_t vd = kd + KV_HALF;
        const char* vg = reinterpret_cast<const char*>(Vbh + (size_t)lrow * DD) + lcb;
        CP_ASYNC16(vd, vg);
        CP_ASYNC16(vd + 16, vg + 16);
        CP_COMMIT();
    }
    CP_WAIT0();
    __syncthreads();

    // hoisted Q fragments
    const int lr = lane & 7;
    const int aRow = warpM + lr + ((lane >> 3) & 1) * 8;
    const int aCb  = ((lane >> 4) & 1) * 16;
    uint32_t qf[4][4];
    #pragma unroll
    for (int ks = 0; ks < 4; ks++)
        LDSM_X4(qf[ks], sb + (uint32_t)(aRow * FROWB + ks * 32 + aCb));

    float m0 = -1e30f, m1 = -1e30f;
    float lacc[4];
    lacc[0] = lacc[1] = lacc[2] = lacc[3] = 0.0f;
    float o[8][4];
    #pragma unroll
    for (int d8 = 0; d8 < 8; d8++)
        #pragma unroll
        for (int r = 0; r < 4; r++) o[d8][r] = 0.0f;

    const int bRowK = lr + ((lane >> 4) & 1) * 8;
    const int bCbK  = ((lane >> 3) & 1) * 16;
    const int vRowB = lr + ((lane >> 3) & 1) * 8;
    const int vCbB  = ((lane >> 4) & 1) * 16;
    const uint32_t ONES = 0x3C003C00u;   // half2(1.0, 1.0)

    for (int kt = 0; kt < 32; kt++) {
        const uint32_t kvb = (kt & 1) ? kvb1 : kvb0;

        if (kt < 31) {
            const int krow = (kt + 1) * 64 + lrow;
            const uint32_t nb = ((kt + 1) & 1) ? kvb1 : kvb0;
            const uint32_t kd = nb + (uint32_t)(lrow * FROWB + lcb);
            const char* kg = reinterpret_cast<const char*>(Kbh + (size_t)krow * DD) + lcb;
            CP_ASYNC16(kd, kg);
            CP_ASYNC16(kd + 16, kg + 16);
            const uint32_t vd = kd + KV_HALF;
            const char* vg = reinterpret_cast<const char*>(Vbh + (size_t)krow * DD) + lcb;
            CP_ASYNC16(vd, vg);
            CP_ASYNC16(vd + 16, vg + 16);
            CP_COMMIT();
        }

        // ---- QK^T ----
        float sc[8][4];
        #pragma unroll
        for (int nb = 0; nb < 8; nb++)
            #pragma unroll
            for (int r = 0; r < 4; r++) sc[nb][r] = 0.0f;
        #pragma unroll
        for (int ks = 0; ks < 4; ks++) {
            #pragma unroll
            for (int ng2 = 0; ng2 < 4; ng2++) {
                uint32_t kf[4];
                LDSM_X4(kf, kvb + (uint32_t)((ng2 * 16 + bRowK) * FROWB + ks * 32 + bCbK));
                mma16816h(sc[2 * ng2 + 0], qf[ks], kf[0], kf[1]);
                mma16816h(sc[2 * ng2 + 1], qf[ks], kf[2], kf[3]);
            }
        }

        // ---- online softmax (scores already * 0.125*log2e) ----
        float mx0 = sc[0][0], mx1 = sc[0][2];
        #pragma unroll
        for (int nb = 0; nb < 8; nb++) {
            mx0 = fmaxf(mx0, fmaxf(sc[nb][0], sc[nb][1]));
            mx1 = fmaxf(mx1, fmaxf(sc[nb][2], sc[nb][3]));
        }
        mx0 = fmaxf(mx0, __shfl_xor_sync(0xffffffffu, mx0, 1));
        mx0 = fmaxf(mx0, __shfl_xor_sync(0xffffffffu, mx0, 2));
        mx1 = fmaxf(mx1, __shfl_xor_sync(0xffffffffu, mx1, 1));
        mx1 = fmaxf(mx1, __shfl_xor_sync(0xffffffffu, mx1, 2));
        const float mn0 = fmaxf(m0, mx0);
        const float mn1 = fmaxf(m1, mx1);
        const float c0 = exp2f(m0 - mn0);
        const float c1 = exp2f(m1 - mn1);
        m0 = mn0; m1 = mn1;

        // p = ex2.approx.f16x2(s - m): fp32 subtract, fp16 exp (packed)
        uint32_t pa0[8], pa1[8];
        #pragma unroll
        for (int nb = 0; nb < 8; nb++) {
            __half2 h0 = __floats2half2_rn(sc[nb][0] - mn0, sc[nb][1] - mn0);
            __half2 h1 = __floats2half2_rn(sc[nb][2] - mn1, sc[nb][3] - mn1);
            pa0[nb] = ex2_h2(*reinterpret_cast<uint32_t*>(&h0));
            pa1[nb] = ex2_h2(*reinterpret_cast<uint32_t*>(&h1));
        }

        // rescale running o and l accumulators
        lacc[0] *= c0; lacc[2] *= c1;
        #pragma unroll
        for (int d8 = 0; d8 < 8; d8++) {
            o[d8][0] *= c0; o[d8][1] *= c0;
            o[d8][2] *= c1; o[d8][3] *= c1;
        }

        // ---- P @ V (+ ones-MMA row sums into lacc) ----
        const uint32_t vbase = kvb + KV_HALF;
        #pragma unroll
        for (int ks = 0; ks < 4; ks++) {
            uint32_t pf[4] = {pa0[2 * ks], pa1[2 * ks], pa0[2 * ks + 1], pa1[2 * ks + 1]};
            mma16816h(lacc, pf, ONES, ONES);
            #pragma unroll
            for (int dg2 = 0; dg2 < 4; dg2++) {
                uint32_t vf[4];
                LDSM_T_X4(vf, vbase + (uint32_t)((ks * 16 + vRowB) * FROWB + dg2 * 32 + vCbB));
                mma16816h(o[2 * dg2 + 0], pf, vf[0], vf[1]);
                mma16816h(o[2 * dg2 + 1], pf, vf[2], vf[3]);
            }
        }

        if (kt < 31) {
            CP_WAIT0();
            __syncthreads();
        }
    }

    // ---- finalize: lacc[0]/lacc[2] are complete row sums (no shuffles) ----
    const float i0 = 1.0f / lacc[0];
    const float i1 = 1.0f / lacc[2];

    const int b = bh >> 4;
    const int h = bh & 15;
    const int g = lane >> 2;
    const int t2 = (lane & 3) * 2;
    const int r0 = q0 + warpM + g;
    __half* d0 = ctx + ((size_t)(b * SS + r0)) * EE + h * DD;
    __half* d1 = ctx + ((size_t)(b * SS + r0 + 8)) * EE + h * DD;
    #pragma unroll
    for (int d8 = 0; d8 < 8; d8++) {
        *reinterpret_cast<__half2*>(d0 + d8 * 8 + t2) =
            __floats2half2_rn(o[d8][0] * i0, o[d8][1] * i0);
        *reinterpret_cast<__half2*>(d1 + d8 * 8 + t2) =
            __floats2half2_rn(o[d8][2] * i1, o[d8][3] * i1);
    }
}

// ---------------- launch ----------------------------------------------------
extern "C" void kernel_launch(void* const* d_in, const int* in_sizes, int n_in,
                              void* d_out, int out_size)
{
    const float* x  = (const float*)d_in[0];
    const float* Wq = (const float*)d_in[1];
    const float* bq = (const float*)d_in[2];
    const float* Wk = (const float*)d_in[3];
    const float* bk = (const float*)d_in[4];
    const float* Wv = (const float*)d_in[5];
    const float* bv = (const float*)d_in[6];
    const float* Wo = (const float*)d_in[7];
    const float* bo = (const float*)d_in[8];
    float* out = (float*)d_out;

    __half *xh, *Wqh, *Wkh, *Wvh, *Woh, *Qp, *Kp, *Vp, *Cp;
    cudaGetSymbolAddress((void**)&xh,  g_xh);
    cudaGetSymbolAddress((void**)&Wqh, g_Wqh);
    cudaGetSymbolAddress((void**)&Wkh, g_Wkh);
    cudaGetSymbolAddress((void**)&Wvh, g_Wvh);
    cudaGetSymbolAddress((void**)&Woh, g_Woh);
    cudaGetSymbolAddress((void**)&Qp,  g_Qh);
    cudaGetSymbolAddress((void**)&Kp,  g_Kh);
    cudaGetSymbolAddress((void**)&Vp,  g_Vh);
    cudaGetSymbolAddress((void**)&Cp,  g_ctxh);

    cudaFuncSetAttribute(gemm_mma_kernel,
                         cudaFuncAttributeMaxDynamicSharedMemorySize, GSMEM_TOTAL);

    // ---- convert inputs to fp16 (x + 4 weights in 2 launches) ----
    const int NW = EE * EE;          // 1M
    const int NX = MM * EE;          // 4M
    cvt_f2h_kernel<<<NX / (256 * 8), 256>>>(x, xh, NX);
    dim3 wGrid(NW / (256 * 8), 4);
    cvt_w_kernel<<<wGrid, 256>>>(Wq, Wk, Wv, Wo, Wqh, Wkh, Wvh, Woh);

    // Q pre-scaled by 0.125 * log2(e) so softmax uses exp2 directly
    const float qscale = 0.18033688011112042f;

    // ---- merged Q/K/V projections (z selects target) ----
    dim3 qkvGrid(EE / 128, MM / 128, 3);   // (8, 32, 3)
    gemm_mma_kernel<<<qkvGrid, 256, GSMEM_TOTAL>>>(
        xh, Wqh, Wkh, Wvh, bq, bk, bv, nullptr, Qp, Kp, Vp, 1, qscale);

    // ---- attention ----
    dim3 faGrid(SS / 128, BB * HH);        // (16, 32)
    flash_mma_kernel<<<faGrid, dim3(256)>>>(Qp, Kp, Vp, Cp);

    // ---- output projection ----
    dim3 oGrid(EE / 128, MM / 128, 1);
    gemm_mma_kernel<<<oGrid, 256, GSMEM_TOTAL>>>(
        Cp, Woh, Woh, Woh, bo, bo, bo, out, nullptr, nullptr, nullptr, 0, 1.0f);
}